// round 1
// baseline (speedup 1.0000x reference)
#include <cuda_runtime.h>
#include <math.h>

// ---------------- scratch (static __device__, no allocations) ----------------
__device__ float g_conv1[8 * 256 * 64 * 64];   // [b][oc][64*64]
__device__ float g_pc1[8 * 512 * 900];         // [b][oc][30*30]
__device__ float g_pc2[8 * 256 * 900];
__device__ float g_pc3[8 * 256 * 784];         // [b][oc][28*28]
__device__ float g_u[8 * 25088 * 8];           // squashed primary caps
__device__ float g_blog[8 * 25088 * 10];       // routing logits
__device__ float g_spart[392 * 1280];          // per-block partial s
__device__ float g_s[1280];                    // s [b][k][j]
__device__ float g_v[1280];                    // v [b][k][j]
__device__ float g_h1[8 * 512];
__device__ float g_h2[8 * 1024];
__device__ float g_rec[8 * 1296];

// ---------------- conv1: 1->256ch, 9x9, relu ----------------
__global__ void conv1_kernel(const float* __restrict__ x,
                             const float* __restrict__ w,
                             const float* __restrict__ bias,
                             float* __restrict__ out) {
    int oc = blockIdx.x, b = blockIdx.y;
    __shared__ float xs[72 * 72];
    __shared__ float wsh[81];
    for (int i = threadIdx.x; i < 5184; i += 256) xs[i] = x[b * 5184 + i];
    if (threadIdx.x < 81) wsh[threadIdx.x] = w[oc * 81 + threadIdx.x];
    __syncthreads();
    float bv = bias[oc];
    for (int i = threadIdx.x; i < 4096; i += 256) {
        int oh = i >> 6, ow = i & 63;
        float acc = bv;
#pragma unroll
        for (int kh = 0; kh < 9; kh++) {
#pragma unroll
            for (int kw = 0; kw < 9; kw++)
                acc += xs[(oh + kh) * 72 + ow + kw] * wsh[kh * 9 + kw];
        }
        out[(b * 256 + oc) * 4096 + i] = fmaxf(acc, 0.f);
    }
}

// ---------------- pc1: 256->512, 5x5, stride 2 (implicit GEMM, tiled) ----------------
// block: 256 threads = 16(tx: spatial) x 16(ty: oc); tile 64 oc x 64 spatial; K chunk 4 ic
__global__ void pc1_kernel(const float* __restrict__ in,
                           const float* __restrict__ w,
                           const float* __restrict__ bias,
                           float* __restrict__ out) {
    int spt = blockIdx.x, oct = blockIdx.y, b = blockIdx.z;
    int oc_base = oct * 64, sp_base = spt * 64;
    int tx = threadIdx.x & 15, ty = threadIdx.x >> 4;
    extern __shared__ float sm[];
    float* ws = sm;          // [4][25][64] (ic,e,oc)
    float* ps = sm + 6400;   // [4][25][64] (ic,e,sp)
    float acc[4][4] = {};
    const float* inb = in + b * 256 * 4096;
    for (int ic0 = 0; ic0 < 256; ic0 += 4) {
        for (int idx = threadIdx.x; idx < 6400; idx += 256) {
            int e = idx % 25;
            int oc = (idx / 25) & 63;
            int ic = idx / 1600;
            ws[ic * 1600 + e * 64 + oc] =
                w[(oc_base + oc) * 6400 + (ic0 + ic) * 25 + e];
        }
        for (int idx = threadIdx.x; idx < 6400; idx += 256) {
            int spi = idx & 63;
            int rest = idx >> 6;
            int e = rest % 25;
            int ic = rest / 25;
            int sp = sp_base + spi;
            float v = 0.f;
            if (sp < 900) {
                int oh = sp / 30, ow = sp - oh * 30;
                int kh = e / 5, kw = e - kh * 5;
                v = inb[(ic0 + ic) * 4096 + (2 * oh + kh) * 64 + (2 * ow + kw)];
            }
            ps[ic * 1600 + e * 64 + spi] = v;
        }
        __syncthreads();
#pragma unroll
        for (int ic = 0; ic < 4; ic++) {
#pragma unroll
            for (int e = 0; e < 25; e++) {
                float4 a = *(const float4*)&ws[ic * 1600 + e * 64 + ty * 4];
                float4 p = *(const float4*)&ps[ic * 1600 + e * 64 + tx * 4];
                acc[0][0] += a.x * p.x; acc[0][1] += a.x * p.y;
                acc[0][2] += a.x * p.z; acc[0][3] += a.x * p.w;
                acc[1][0] += a.y * p.x; acc[1][1] += a.y * p.y;
                acc[1][2] += a.y * p.z; acc[1][3] += a.y * p.w;
                acc[2][0] += a.z * p.x; acc[2][1] += a.z * p.y;
                acc[2][2] += a.z * p.z; acc[2][3] += a.z * p.w;
                acc[3][0] += a.w * p.x; acc[3][1] += a.w * p.y;
                acc[3][2] += a.w * p.z; acc[3][3] += a.w * p.w;
            }
        }
        __syncthreads();
    }
#pragma unroll
    for (int i = 0; i < 4; i++) {
        int oc = oc_base + ty * 4 + i;
        float bv = bias[oc];
#pragma unroll
        for (int jj = 0; jj < 4; jj++) {
            int sp = sp_base + tx * 4 + jj;
            if (sp < 900) out[(b * 512 + oc) * 900 + sp] = acc[i][jj] + bv;
        }
    }
}

// ---------------- pc2: grouped 32g, 16->8, 3x3, pad 1 ----------------
__global__ void pc2_kernel(const float* __restrict__ in,
                           const float* __restrict__ w,
                           const float* __restrict__ bias,
                           float* __restrict__ out) {
    int g = blockIdx.x, b = blockIdx.y;
    __shared__ float wsh[8 * 16 * 9];
    for (int idx = threadIdx.x; idx < 1152; idx += 256) wsh[idx] = w[g * 1152 + idx];
    __syncthreads();
    const float* inb = in + (b * 512 + g * 16) * 900;
    for (int sp = threadIdx.x; sp < 900; sp += 256) {
        int oh = sp / 30, ow = sp - oh * 30;
        float acc[8];
#pragma unroll
        for (int o = 0; o < 8; o++) acc[o] = bias[g * 8 + o];
        for (int i = 0; i < 16; i++) {
            const float* ip = inb + i * 900;
#pragma unroll
            for (int kh = 0; kh < 3; kh++) {
                int ih = oh - 1 + kh;
                if (ih < 0 || ih >= 30) continue;
#pragma unroll
                for (int kw = 0; kw < 3; kw++) {
                    int iw = ow - 1 + kw;
                    if (iw < 0 || iw >= 30) continue;
                    float v = ip[ih * 30 + iw];
                    int e = kh * 3 + kw;
#pragma unroll
                    for (int o = 0; o < 8; o++) acc[o] += v * wsh[(o * 16 + i) * 9 + e];
                }
            }
        }
#pragma unroll
        for (int o = 0; o < 8; o++) out[(b * 256 + g * 8 + o) * 900 + sp] = acc[o];
    }
}

// ---------------- pc3: grouped 32g, 8->8, 3x3, pad 0 (30->28) ----------------
__global__ void pc3_kernel(const float* __restrict__ in,
                           const float* __restrict__ w,
                           const float* __restrict__ bias,
                           float* __restrict__ out) {
    int g = blockIdx.x, b = blockIdx.y;
    __shared__ float wsh[8 * 8 * 9];
    for (int idx = threadIdx.x; idx < 576; idx += 256) wsh[idx] = w[g * 576 + idx];
    __syncthreads();
    const float* inb = in + (b * 256 + g * 8) * 900;
    for (int sp = threadIdx.x; sp < 784; sp += 256) {
        int oh = sp / 28, ow = sp - oh * 28;
        float acc[8];
#pragma unroll
        for (int o = 0; o < 8; o++) acc[o] = bias[g * 8 + o];
        for (int i = 0; i < 8; i++) {
            const float* ip = inb + i * 900;
#pragma unroll
            for (int kh = 0; kh < 3; kh++) {
#pragma unroll
                for (int kw = 0; kw < 3; kw++) {
                    float v = ip[(oh + kh) * 30 + (ow + kw)];
                    int e = kh * 3 + kw;
#pragma unroll
                    for (int o = 0; o < 8; o++) acc[o] += v * wsh[(o * 8 + i) * 9 + e];
                }
            }
        }
#pragma unroll
        for (int o = 0; o < 8; o++) out[(b * 256 + g * 8 + o) * 784 + sp] = acc[o];
    }
}

// ---------------- build u (capsule transpose) + squash over dim 8 ----------------
// u[b, s*32+cap, d] = squash( y[b, cap*8+d, s] )
__global__ void u_build_kernel(const float* __restrict__ y, float* __restrict__ u) {
    int b = blockIdx.y;
    int s0 = blockIdx.x * 16;
    __shared__ float ys[256 * 16];  // [ch][si]
    for (int i = threadIdx.x; i < 4096; i += 256) {
        int ch = i >> 4, si = i & 15;
        ys[i] = y[(b * 256 + ch) * 784 + s0 + si];
    }
    __syncthreads();
    for (int p = threadIdx.x; p < 512; p += 256) {
        int si = p >> 5, cap = p & 31;
        float d[8];
        float sq = 0.f;
#pragma unroll
        for (int i = 0; i < 8; i++) {
            d[i] = ys[(cap * 8 + i) * 16 + si];
            sq += d[i] * d[i];
        }
        float f = sq / (sqrtf(sq) * (1.f + sq));
        int n = (s0 + si) * 32 + cap;
        float* up = u + (b * 25088 + n) * 8;
#pragma unroll
        for (int i = 0; i < 8; i++) up[i] = f * d[i];
    }
}

// ---------------- fused routing pass ----------------
// mode 0: c = 0.1 (b_logits = 0), no logit IO
// mode 1: bl = u_hat.v ; write g_blog ; c = softmax(bl)
// mode 2: bl = g_blog + u_hat.v ; c = softmax(bl)  (no write)
// warp layout: lane = bhalf*16 + j ; loop bp covers b = bp*2+bhalf
__global__ void routing_kernel(const float* __restrict__ W, int mode) {
    int warp = (blockIdx.x * 256 + threadIdx.x) >> 5;
    int lane = threadIdx.x & 31;
    int bhalf = lane >> 4;
    int j = lane & 15;
    float s_acc[4][10];
#pragma unroll
    for (int bp = 0; bp < 4; bp++)
#pragma unroll
        for (int k = 0; k < 10; k++) s_acc[bp][k] = 0.f;

    int n0 = warp * 8;
    for (int nn = 0; nn < 8; nn++) {
        int n = n0 + nn;
        const float* Wn = W + (size_t)n * 1280;
#pragma unroll
        for (int bp = 0; bp < 4; bp++) {
            int b = bp * 2 + bhalf;
            const float* up = g_u + (b * 25088 + n) * 8;
            float uu[8];
#pragma unroll
            for (int i = 0; i < 8; i++) uu[i] = up[i];
            float uh[10];
#pragma unroll
            for (int k = 0; k < 10; k++) {
                float a = 0.f;
#pragma unroll
                for (int i = 0; i < 8; i++) a += uu[i] * Wn[k * 128 + i * 16 + j];
                uh[k] = a;
            }
            float c[10];
            if (mode == 0) {
#pragma unroll
                for (int k = 0; k < 10; k++) c[k] = 0.1f;
            } else {
                float bl[10];
#pragma unroll
                for (int k = 0; k < 10; k++) {
                    float d = uh[k] * g_v[(b * 10 + k) * 16 + j];
                    d += __shfl_xor_sync(0xffffffffu, d, 1);
                    d += __shfl_xor_sync(0xffffffffu, d, 2);
                    d += __shfl_xor_sync(0xffffffffu, d, 4);
                    d += __shfl_xor_sync(0xffffffffu, d, 8);
                    bl[k] = d;
                }
                if (mode == 2) {
#pragma unroll
                    for (int k = 0; k < 10; k++)
                        bl[k] += g_blog[(b * 25088 + n) * 10 + k];
                } else if (j == 0) {
#pragma unroll
                    for (int k = 0; k < 10; k++)
                        g_blog[(b * 25088 + n) * 10 + k] = bl[k];
                }
                float m = bl[0];
#pragma unroll
                for (int k = 1; k < 10; k++) m = fmaxf(m, bl[k]);
                float sum = 0.f;
#pragma unroll
                for (int k = 0; k < 10; k++) { c[k] = expf(bl[k] - m); sum += c[k]; }
                float inv = 1.f / sum;
#pragma unroll
                for (int k = 0; k < 10; k++) c[k] *= inv;
            }
#pragma unroll
            for (int k = 0; k < 10; k++) s_acc[bp][k] += c[k] * uh[k];
        }
    }
    // deterministic block reduction: each warp owns a distinct smem slab
    __shared__ float ssm[8][1280];
    int wl = (threadIdx.x >> 5);
#pragma unroll
    for (int bp = 0; bp < 4; bp++) {
        int b = bp * 2 + bhalf;
#pragma unroll
        for (int k = 0; k < 10; k++)
            ssm[wl][(b * 10 + k) * 16 + j] = s_acc[bp][k];
    }
    __syncthreads();
    for (int i = threadIdx.x; i < 1280; i += 256) {
        float t = 0.f;
#pragma unroll
        for (int w = 0; w < 8; w++) t += ssm[w][i];
        g_spart[blockIdx.x * 1280 + i] = t;
    }
}

__global__ void reduce_s_kernel() {
    int i = blockIdx.x * 256 + threadIdx.x;
    if (i < 1280) {
        float t = 0.f;
        for (int p = 0; p < 392; p++) t += g_spart[p * 1280 + i];
        g_s[i] = t;
    }
}

__global__ void squash_v_kernel(float* out_opt) {
    int t = threadIdx.x;
    if (t < 80) {
        int base = t * 16;
        float sv[16];
        float sq = 0.f;
#pragma unroll
        for (int jj = 0; jj < 16; jj++) { sv[jj] = g_s[base + jj]; sq += sv[jj] * sv[jj]; }
        float f = sq / (sqrtf(sq) * (1.f + sq));
#pragma unroll
        for (int jj = 0; jj < 16; jj++) {
            float vv = f * sv[jj];
            g_v[base + jj] = vv;
            if (out_opt) out_opt[base + jj] = vv;
        }
    }
}

// ---------------- decoder ----------------
__global__ void fc1_kernel(const float* __restrict__ target,
                           const float* __restrict__ w,
                           const float* __restrict__ bias) {
    int b = blockIdx.x;
    __shared__ float vm[16];
    if (threadIdx.x < 16) {
        float a = 0.f;
        for (int k = 0; k < 10; k++) a += target[b * 10 + k] * g_v[(b * 10 + k) * 16 + threadIdx.x];
        vm[threadIdx.x] = a;
    }
    __syncthreads();
    int o = threadIdx.x;
    float acc = bias[o];
#pragma unroll
    for (int i = 0; i < 16; i++) acc += vm[i] * w[o * 16 + i];
    g_h1[b * 512 + o] = fmaxf(acc, 0.f);
}

__global__ void fc2_kernel(const float* __restrict__ w, const float* __restrict__ bias) {
    int b = blockIdx.x;
    __shared__ float h1[512];
    if (threadIdx.x < 512) h1[threadIdx.x] = g_h1[b * 512 + threadIdx.x];
    __syncthreads();
    int o = threadIdx.x;
    float acc = bias[o];
    for (int i = 0; i < 512; i++) acc += h1[i] * w[o * 512 + i];
    g_h2[b * 1024 + o] = fmaxf(acc, 0.f);
}

__global__ void fc3_kernel(const float* __restrict__ w, const float* __restrict__ bias) {
    int b = blockIdx.y;
    int o = blockIdx.x * 256 + threadIdx.x;
    __shared__ float h2[1024];
    for (int i = threadIdx.x; i < 1024; i += 256) h2[i] = g_h2[b * 1024 + i];
    __syncthreads();
    if (o < 1296) {
        float acc = bias[o];
        for (int i = 0; i < 1024; i++) acc += h2[i] * w[o * 1024 + i];
        g_rec[b * 1296 + o] = 1.f / (1.f + expf(-acc));
    }
}

__global__ void upsample_kernel(float* __restrict__ out) {
    int idx = blockIdx.x * 256 + threadIdx.x;
    if (idx >= 8 * 5184) return;
    int b = idx / 5184;
    int r = idx - b * 5184;
    int oy = r / 72, ox = r - oy * 72;
    float sy = (float)(oy * 35) / 71.0f;
    float sx = (float)(ox * 35) / 71.0f;
    int y0 = (int)sy, x0 = (int)sx;
    int y1 = min(y0 + 1, 35), x1 = min(x0 + 1, 35);
    float wy = sy - (float)y0, wx = sx - (float)x0;
    const float* rb = g_rec + b * 1296;
    float a00 = rb[y0 * 36 + x0], a01 = rb[y0 * 36 + x1];
    float a10 = rb[y1 * 36 + x0], a11 = rb[y1 * 36 + x1];
    float v = (1.f - wy) * ((1.f - wx) * a00 + wx * a01) +
              wy * ((1.f - wx) * a10 + wx * a11);
    out[1280 + b * 5184 + r] = v;
}

// ---------------- launch ----------------
extern "C" void kernel_launch(void* const* d_in, const int* in_sizes, int n_in,
                              void* d_out, int out_size) {
    const float* x       = (const float*)d_in[0];
    const float* target  = (const float*)d_in[1];
    const float* conv1_w = (const float*)d_in[2];
    const float* conv1_b = (const float*)d_in[3];
    const float* pc1_w   = (const float*)d_in[4];
    const float* pc1_b   = (const float*)d_in[5];
    const float* pc2_w   = (const float*)d_in[6];
    const float* pc2_b   = (const float*)d_in[7];
    const float* pc3_w   = (const float*)d_in[8];
    const float* pc3_b   = (const float*)d_in[9];
    const float* W_digit = (const float*)d_in[10];
    const float* fc1_w   = (const float*)d_in[11];
    const float* fc1_b   = (const float*)d_in[12];
    const float* fc2_w   = (const float*)d_in[13];
    const float* fc2_b   = (const float*)d_in[14];
    const float* fc3_w   = (const float*)d_in[15];
    const float* fc3_b   = (const float*)d_in[16];
    float* out = (float*)d_out;

    float *conv1p, *pc1p, *pc2p, *pc3p, *up;
    cudaGetSymbolAddress((void**)&conv1p, g_conv1);
    cudaGetSymbolAddress((void**)&pc1p, g_pc1);
    cudaGetSymbolAddress((void**)&pc2p, g_pc2);
    cudaGetSymbolAddress((void**)&pc3p, g_pc3);
    cudaGetSymbolAddress((void**)&up, g_u);

    cudaFuncSetAttribute(pc1_kernel, cudaFuncAttributeMaxDynamicSharedMemorySize, 51200);

    conv1_kernel<<<dim3(256, 8), 256>>>(x, conv1_w, conv1_b, conv1p);
    pc1_kernel<<<dim3(15, 8, 8), 256, 51200>>>(conv1p, pc1_w, pc1_b, pc1p);
    pc2_kernel<<<dim3(32, 8), 256>>>(pc1p, pc2_w, pc2_b, pc2p);
    pc3_kernel<<<dim3(32, 8), 256>>>(pc2p, pc3_w, pc3_b, pc3p);
    u_build_kernel<<<dim3(49, 8), 256>>>(pc3p, up);

    // routing iteration 1 (uniform c)
    routing_kernel<<<392, 256>>>(W_digit, 0);
    reduce_s_kernel<<<5, 256>>>();
    squash_v_kernel<<<1, 96>>>(nullptr);
    // routing iteration 2
    routing_kernel<<<392, 256>>>(W_digit, 1);
    reduce_s_kernel<<<5, 256>>>();
    squash_v_kernel<<<1, 96>>>(nullptr);
    // routing iteration 3 (final v -> d_out[0:1280])
    routing_kernel<<<392, 256>>>(W_digit, 2);
    reduce_s_kernel<<<5, 256>>>();
    squash_v_kernel<<<1, 96>>>(out);

    // decoder
    fc1_kernel<<<8, 512>>>(target, fc1_w, fc1_b);
    fc2_kernel<<<8, 1024>>>(fc2_w, fc2_b);
    fc3_kernel<<<dim3(6, 8), 256>>>(fc3_w, fc3_b);
    upsample_kernel<<<162, 256>>>(out);
}

// round 2
// speedup vs baseline: 1.5515x; 1.5515x over previous
#include <cuda_runtime.h>
#include <math.h>

// ---------------- scratch (static __device__, no allocations) ----------------
__device__ float g_conv1[8 * 256 * 64 * 64];   // [b][oc][64*64]
__device__ float g_wT[6400 * 512];             // pc1 weights transposed [k][oc]
__device__ float g_pc1[8 * 512 * 900];         // [b][oc][30*30]
__device__ float g_pc2[8 * 256 * 900];
__device__ float g_pc3[8 * 256 * 784];         // [b][oc][28*28]
__device__ float g_u[8 * 25088 * 8];           // squashed primary caps
__device__ float g_blog[8 * 25088 * 10];       // routing logits
__device__ float g_spart[392 * 1280];          // per-block partial s
__device__ float g_s[1280];                    // s [b][k][j]
__device__ float g_v[1280];                    // v [b][k][j]
__device__ float g_h1[8 * 512];
__device__ float g_h2[8 * 1024];
__device__ float g_rec[8 * 1296];

// ---------------- conv1: 1->256ch, 9x9, relu ----------------
__global__ void conv1_kernel(const float* __restrict__ x,
                             const float* __restrict__ w,
                             const float* __restrict__ bias,
                             float* __restrict__ out) {
    int oc = blockIdx.x, b = blockIdx.y;
    __shared__ float xs[72 * 72];
    __shared__ float wsh[81];
    for (int i = threadIdx.x; i < 5184; i += 256) xs[i] = x[b * 5184 + i];
    if (threadIdx.x < 81) wsh[threadIdx.x] = w[oc * 81 + threadIdx.x];
    __syncthreads();
    float bv = bias[oc];
    for (int i = threadIdx.x; i < 4096; i += 256) {
        int oh = i >> 6, ow = i & 63;
        float acc = bv;
#pragma unroll
        for (int kh = 0; kh < 9; kh++) {
#pragma unroll
            for (int kw = 0; kw < 9; kw++)
                acc += xs[(oh + kh) * 72 + ow + kw] * wsh[kh * 9 + kw];
        }
        out[(b * 256 + oc) * 4096 + i] = fmaxf(acc, 0.f);
    }
}

// ---------------- transpose pc1 weights: [512][6400] -> [6400][512] ----------------
__global__ void transpose_w_kernel(const float* __restrict__ w, float* __restrict__ wt) {
    __shared__ float t[32][33];
    int kk0 = blockIdx.x * 32, oc0 = blockIdx.y * 32;
    int x = threadIdx.x, y = threadIdx.y;  // block (32, 8)
#pragma unroll
    for (int i = y; i < 32; i += 8)
        t[i][x] = w[(oc0 + i) * 6400 + kk0 + x];
    __syncthreads();
#pragma unroll
    for (int i = y; i < 32; i += 8)
        wt[(kk0 + i) * 512 + oc0 + x] = t[x][i];
}

// ---------------- pc1: 256->512, 5x5, stride 2 — 128x128 tile SGEMM ----------------
// C[oc, sp] = sum_k WT[k][oc] * Im2col[k][sp],  K = 6400 (k = ic*25 + e)
// 256 threads: tx = tid%16 (sp dim), ty = tid/16 (oc dim); thread tile 8x8
__global__ void __launch_bounds__(256, 2)
pc1_kernel(const float* __restrict__ in,
           const float* __restrict__ wt,
           const float* __restrict__ bias,
           float* __restrict__ out) {
    int spt = blockIdx.x, oct = blockIdx.y, b = blockIdx.z;
    int oc_base = oct * 128, sp_base = spt * 128;
    int tid = threadIdx.x;
    int tx = tid & 15, ty = tid >> 4;
    extern __shared__ float sm[];
    float* As = sm;            // [50][128] k-chunk x oc
    float* Bs = sm + 6400;     // [50][128] k-chunk x sp

    // per-thread B-load geometry (fixed across chunks)
    int spi = tid & 127;
    int hi = tid >> 7;         // 0 or 1 -> even/odd ke rows
    int sp = sp_base + spi;
    bool valid = sp < 900;
    int oh = valid ? sp / 30 : 0;
    int ow = valid ? sp - oh * 30 : 0;
    int p0 = (2 * oh) * 64 + 2 * ow;
    const float* inb = in + (size_t)b * 256 * 4096;

    float acc[8][8];
#pragma unroll
    for (int i = 0; i < 8; i++)
#pragma unroll
        for (int j = 0; j < 8; j++) acc[i][j] = 0.f;

    for (int ic0 = 0; ic0 < 256; ic0 += 2) {
        // load A: 50x128 from WT (coalesced, conflict-free stores)
        const float* wtc = wt + (size_t)(ic0 * 25) * 512 + oc_base;
#pragma unroll
        for (int t = 0; t < 25; t++) {
            int idx = t * 256 + tid;
            int oc = idx & 127, ke = idx >> 7;
            As[ke * 128 + oc] = wtc[ke * 512 + oc];
        }
        // load B: im2col 50x128
#pragma unroll
        for (int t = 0; t < 25; t++) {
            int ke = 2 * t + hi;
            int e = ke % 25, ic = ke / 25;
            int kh = e / 5, kw = e - kh * 5;
            float v = 0.f;
            if (valid) v = inb[(ic0 + ic) * 4096 + p0 + kh * 64 + kw];
            Bs[ke * 128 + spi] = v;
        }
        __syncthreads();
#pragma unroll 5
        for (int ke = 0; ke < 50; ke++) {
            float4 a0 = *(const float4*)&As[ke * 128 + ty * 8];
            float4 a1 = *(const float4*)&As[ke * 128 + ty * 8 + 4];
            float4 b0 = *(const float4*)&Bs[ke * 128 + tx * 8];
            float4 b1 = *(const float4*)&Bs[ke * 128 + tx * 8 + 4];
            float av[8] = {a0.x, a0.y, a0.z, a0.w, a1.x, a1.y, a1.z, a1.w};
            float bv[8] = {b0.x, b0.y, b0.z, b0.w, b1.x, b1.y, b1.z, b1.w};
#pragma unroll
            for (int i = 0; i < 8; i++)
#pragma unroll
                for (int j = 0; j < 8; j++) acc[i][j] += av[i] * bv[j];
        }
        __syncthreads();
    }
#pragma unroll
    for (int i = 0; i < 8; i++) {
        int oc = oc_base + ty * 8 + i;
        float bb = bias[oc];
        float* op = out + ((size_t)b * 512 + oc) * 900;
#pragma unroll
        for (int j = 0; j < 8; j++) {
            int s2 = sp_base + tx * 8 + j;
            if (s2 < 900) op[s2] = acc[i][j] + bb;
        }
    }
}

// ---------------- pc2: grouped 32g, 16->8, 3x3, pad 1 (smem input) ----------------
__global__ void pc2_kernel(const float* __restrict__ in,
                           const float* __restrict__ w,
                           const float* __restrict__ bias,
                           float* __restrict__ out) {
    int g = blockIdx.x, b = blockIdx.y;
    extern __shared__ float sm2[];
    float* wsh = sm2;            // 1152
    float* xin = sm2 + 1152;     // 16*900
    for (int idx = threadIdx.x; idx < 1152; idx += 256) wsh[idx] = w[g * 1152 + idx];
    const float* inb = in + ((size_t)b * 512 + g * 16) * 900;
    for (int idx = threadIdx.x; idx < 14400; idx += 256) xin[idx] = inb[idx];
    __syncthreads();
    for (int sp = threadIdx.x; sp < 900; sp += 256) {
        int oh = sp / 30, ow = sp - oh * 30;
        float acc[8];
#pragma unroll
        for (int o = 0; o < 8; o++) acc[o] = bias[g * 8 + o];
        for (int i = 0; i < 16; i++) {
            const float* ip = xin + i * 900;
#pragma unroll
            for (int kh = 0; kh < 3; kh++) {
                int ih = oh - 1 + kh;
                if (ih < 0 || ih >= 30) continue;
#pragma unroll
                for (int kw = 0; kw < 3; kw++) {
                    int iw = ow - 1 + kw;
                    if (iw < 0 || iw >= 30) continue;
                    float v = ip[ih * 30 + iw];
                    int e = kh * 3 + kw;
#pragma unroll
                    for (int o = 0; o < 8; o++) acc[o] += v * wsh[(o * 16 + i) * 9 + e];
                }
            }
        }
#pragma unroll
        for (int o = 0; o < 8; o++) out[((size_t)b * 256 + g * 8 + o) * 900 + sp] = acc[o];
    }
}

// ---------------- pc3: grouped 32g, 8->8, 3x3, pad 0 (30->28) (smem input) ----------------
__global__ void pc3_kernel(const float* __restrict__ in,
                           const float* __restrict__ w,
                           const float* __restrict__ bias,
                           float* __restrict__ out) {
    int g = blockIdx.x, b = blockIdx.y;
    __shared__ float wsh[576];
    __shared__ float xin[8 * 900];
    for (int idx = threadIdx.x; idx < 576; idx += 256) wsh[idx] = w[g * 576 + idx];
    const float* inb = in + ((size_t)b * 256 + g * 8) * 900;
    for (int idx = threadIdx.x; idx < 7200; idx += 256) xin[idx] = inb[idx];
    __syncthreads();
    for (int sp = threadIdx.x; sp < 784; sp += 256) {
        int oh = sp / 28, ow = sp - oh * 28;
        float acc[8];
#pragma unroll
        for (int o = 0; o < 8; o++) acc[o] = bias[g * 8 + o];
        for (int i = 0; i < 8; i++) {
            const float* ip = xin + i * 900;
#pragma unroll
            for (int kh = 0; kh < 3; kh++) {
#pragma unroll
                for (int kw = 0; kw < 3; kw++) {
                    float v = ip[(oh + kh) * 30 + (ow + kw)];
                    int e = kh * 3 + kw;
#pragma unroll
                    for (int o = 0; o < 8; o++) acc[o] += v * wsh[(o * 8 + i) * 9 + e];
                }
            }
        }
#pragma unroll
        for (int o = 0; o < 8; o++) out[((size_t)b * 256 + g * 8 + o) * 784 + sp] = acc[o];
    }
}

// ---------------- build u (capsule transpose) + squash over dim 8 ----------------
__global__ void u_build_kernel(const float* __restrict__ y, float* __restrict__ u) {
    int b = blockIdx.y;
    int s0 = blockIdx.x * 16;
    __shared__ float ys[256 * 16];  // [ch][si]
    for (int i = threadIdx.x; i < 4096; i += 256) {
        int ch = i >> 4, si = i & 15;
        ys[i] = y[(b * 256 + ch) * 784 + s0 + si];
    }
    __syncthreads();
    for (int p = threadIdx.x; p < 512; p += 256) {
        int si = p >> 5, cap = p & 31;
        float d[8];
        float sq = 0.f;
#pragma unroll
        for (int i = 0; i < 8; i++) {
            d[i] = ys[(cap * 8 + i) * 16 + si];
            sq += d[i] * d[i];
        }
        float f = sq / (sqrtf(sq) * (1.f + sq));
        int n = (s0 + si) * 32 + cap;
        float* up = u + ((size_t)b * 25088 + n) * 8;
#pragma unroll
        for (int i = 0; i < 8; i++) up[i] = f * d[i];
    }
}

// ---------------- fused routing pass ----------------
__global__ void routing_kernel(const float* __restrict__ W, int mode) {
    int warp = (blockIdx.x * 256 + threadIdx.x) >> 5;
    int lane = threadIdx.x & 31;
    int bhalf = lane >> 4;
    int j = lane & 15;
    float s_acc[4][10];
#pragma unroll
    for (int bp = 0; bp < 4; bp++)
#pragma unroll
        for (int k = 0; k < 10; k++) s_acc[bp][k] = 0.f;

    int n0 = warp * 8;
    for (int nn = 0; nn < 8; nn++) {
        int n = n0 + nn;
        const float* Wn = W + (size_t)n * 1280;
#pragma unroll
        for (int bp = 0; bp < 4; bp++) {
            int b = bp * 2 + bhalf;
            const float* up = g_u + ((size_t)b * 25088 + n) * 8;
            float uu[8];
#pragma unroll
            for (int i = 0; i < 8; i++) uu[i] = up[i];
            float uh[10];
#pragma unroll
            for (int k = 0; k < 10; k++) {
                float a = 0.f;
#pragma unroll
                for (int i = 0; i < 8; i++) a += uu[i] * Wn[k * 128 + i * 16 + j];
                uh[k] = a;
            }
            float c[10];
            if (mode == 0) {
#pragma unroll
                for (int k = 0; k < 10; k++) c[k] = 0.1f;
            } else {
                float bl[10];
#pragma unroll
                for (int k = 0; k < 10; k++) {
                    float d = uh[k] * g_v[(b * 10 + k) * 16 + j];
                    d += __shfl_xor_sync(0xffffffffu, d, 1);
                    d += __shfl_xor_sync(0xffffffffu, d, 2);
                    d += __shfl_xor_sync(0xffffffffu, d, 4);
                    d += __shfl_xor_sync(0xffffffffu, d, 8);
                    bl[k] = d;
                }
                if (mode == 2) {
#pragma unroll
                    for (int k = 0; k < 10; k++)
                        bl[k] += g_blog[((size_t)b * 25088 + n) * 10 + k];
                } else if (j == 0) {
#pragma unroll
                    for (int k = 0; k < 10; k++)
                        g_blog[((size_t)b * 25088 + n) * 10 + k] = bl[k];
                }
                float m = bl[0];
#pragma unroll
                for (int k = 1; k < 10; k++) m = fmaxf(m, bl[k]);
                float sum = 0.f;
#pragma unroll
                for (int k = 0; k < 10; k++) { c[k] = expf(bl[k] - m); sum += c[k]; }
                float inv = 1.f / sum;
#pragma unroll
                for (int k = 0; k < 10; k++) c[k] *= inv;
            }
#pragma unroll
            for (int k = 0; k < 10; k++) s_acc[bp][k] += c[k] * uh[k];
        }
    }
    __shared__ float ssm[8][1280];
    int wl = (threadIdx.x >> 5);
#pragma unroll
    for (int bp = 0; bp < 4; bp++) {
        int b = bp * 2 + bhalf;
#pragma unroll
        for (int k = 0; k < 10; k++)
            ssm[wl][(b * 10 + k) * 16 + j] = s_acc[bp][k];
    }
    __syncthreads();
    for (int i = threadIdx.x; i < 1280; i += 256) {
        float t = 0.f;
#pragma unroll
        for (int w = 0; w < 8; w++) t += ssm[w][i];
        g_spart[blockIdx.x * 1280 + i] = t;
    }
}

__global__ void reduce_s_kernel() {
    int i = blockIdx.x * 256 + threadIdx.x;
    if (i < 1280) {
        float t = 0.f;
        for (int p = 0; p < 392; p++) t += g_spart[p * 1280 + i];
        g_s[i] = t;
    }
}

__global__ void squash_v_kernel(float* out_opt) {
    int t = threadIdx.x;
    if (t < 80) {
        int base = t * 16;
        float sv[16];
        float sq = 0.f;
#pragma unroll
        for (int jj = 0; jj < 16; jj++) { sv[jj] = g_s[base + jj]; sq += sv[jj] * sv[jj]; }
        float f = sq / (sqrtf(sq) * (1.f + sq));
#pragma unroll
        for (int jj = 0; jj < 16; jj++) {
            float vv = f * sv[jj];
            g_v[base + jj] = vv;
            if (out_opt) out_opt[base + jj] = vv;
        }
    }
}

// ---------------- decoder ----------------
__global__ void fc1_kernel(const float* __restrict__ target,
                           const float* __restrict__ w,
                           const float* __restrict__ bias) {
    int b = blockIdx.x;
    __shared__ float vm[16];
    if (threadIdx.x < 16) {
        float a = 0.f;
        for (int k = 0; k < 10; k++) a += target[b * 10 + k] * g_v[(b * 10 + k) * 16 + threadIdx.x];
        vm[threadIdx.x] = a;
    }
    __syncthreads();
    int o = threadIdx.x;
    float acc = bias[o];
#pragma unroll
    for (int i = 0; i < 16; i++) acc += vm[i] * w[o * 16 + i];
    g_h1[b * 512 + o] = fmaxf(acc, 0.f);
}

__global__ void fc2_kernel(const float* __restrict__ w, const float* __restrict__ bias) {
    int b = blockIdx.x;
    __shared__ float h1[512];
    if (threadIdx.x < 512) h1[threadIdx.x] = g_h1[b * 512 + threadIdx.x];
    __syncthreads();
    int o = threadIdx.x;
    float acc = bias[o];
    for (int i = 0; i < 512; i++) acc += h1[i] * w[o * 512 + i];
    g_h2[b * 1024 + o] = fmaxf(acc, 0.f);
}

__global__ void fc3_kernel(const float* __restrict__ w, const float* __restrict__ bias) {
    int b = blockIdx.y;
    int o = blockIdx.x * 256 + threadIdx.x;
    __shared__ float h2[1024];
    for (int i = threadIdx.x; i < 1024; i += 256) h2[i] = g_h2[b * 1024 + i];
    __syncthreads();
    if (o < 1296) {
        float acc = bias[o];
        for (int i = 0; i < 1024; i++) acc += h2[i] * w[o * 1024 + i];
        g_rec[b * 1296 + o] = 1.f / (1.f + expf(-acc));
    }
}

__global__ void upsample_kernel(float* __restrict__ out) {
    int idx = blockIdx.x * 256 + threadIdx.x;
    if (idx >= 8 * 5184) return;
    int b = idx / 5184;
    int r = idx - b * 5184;
    int oy = r / 72, ox = r - oy * 72;
    float sy = (float)(oy * 35) / 71.0f;
    float sx = (float)(ox * 35) / 71.0f;
    int y0 = (int)sy, x0 = (int)sx;
    int y1 = min(y0 + 1, 35), x1 = min(x0 + 1, 35);
    float wy = sy - (float)y0, wx = sx - (float)x0;
    const float* rb = g_rec + b * 1296;
    float a00 = rb[y0 * 36 + x0], a01 = rb[y0 * 36 + x1];
    float a10 = rb[y1 * 36 + x0], a11 = rb[y1 * 36 + x1];
    float v = (1.f - wy) * ((1.f - wx) * a00 + wx * a01) +
              wy * ((1.f - wx) * a10 + wx * a11);
    out[1280 + b * 5184 + r] = v;
}

// ---------------- launch ----------------
extern "C" void kernel_launch(void* const* d_in, const int* in_sizes, int n_in,
                              void* d_out, int out_size) {
    const float* x       = (const float*)d_in[0];
    const float* target  = (const float*)d_in[1];
    const float* conv1_w = (const float*)d_in[2];
    const float* conv1_b = (const float*)d_in[3];
    const float* pc1_w   = (const float*)d_in[4];
    const float* pc1_b   = (const float*)d_in[5];
    const float* pc2_w   = (const float*)d_in[6];
    const float* pc2_b   = (const float*)d_in[7];
    const float* pc3_w   = (const float*)d_in[8];
    const float* pc3_b   = (const float*)d_in[9];
    const float* W_digit = (const float*)d_in[10];
    const float* fc1_w   = (const float*)d_in[11];
    const float* fc1_b   = (const float*)d_in[12];
    const float* fc2_w   = (const float*)d_in[13];
    const float* fc2_b   = (const float*)d_in[14];
    const float* fc3_w   = (const float*)d_in[15];
    const float* fc3_b   = (const float*)d_in[16];
    float* out = (float*)d_out;

    float *conv1p, *wtp, *pc1p, *pc2p, *pc3p, *up;
    cudaGetSymbolAddress((void**)&conv1p, g_conv1);
    cudaGetSymbolAddress((void**)&wtp, g_wT);
    cudaGetSymbolAddress((void**)&pc1p, g_pc1);
    cudaGetSymbolAddress((void**)&pc2p, g_pc2);
    cudaGetSymbolAddress((void**)&pc3p, g_pc3);
    cudaGetSymbolAddress((void**)&up, g_u);

    cudaFuncSetAttribute(pc1_kernel, cudaFuncAttributeMaxDynamicSharedMemorySize, 51200);
    cudaFuncSetAttribute(pc2_kernel, cudaFuncAttributeMaxDynamicSharedMemorySize, 62208);

    conv1_kernel<<<dim3(256, 8), 256>>>(x, conv1_w, conv1_b, conv1p);
    transpose_w_kernel<<<dim3(200, 16), dim3(32, 8)>>>(pc1_w, wtp);
    pc1_kernel<<<dim3(8, 4, 8), 256, 51200>>>(conv1p, wtp, pc1_b, pc1p);
    pc2_kernel<<<dim3(32, 8), 256, 62208>>>(pc1p, pc2_w, pc2_b, pc2p);
    pc3_kernel<<<dim3(32, 8), 256>>>(pc2p, pc3_w, pc3_b, pc3p);
    u_build_kernel<<<dim3(49, 8), 256>>>(pc3p, up);

    // routing iteration 1 (uniform c)
    routing_kernel<<<392, 256>>>(W_digit, 0);
    reduce_s_kernel<<<5, 256>>>();
    squash_v_kernel<<<1, 96>>>(nullptr);
    // routing iteration 2
    routing_kernel<<<392, 256>>>(W_digit, 1);
    reduce_s_kernel<<<5, 256>>>();
    squash_v_kernel<<<1, 96>>>(nullptr);
    // routing iteration 3 (final v -> d_out[0:1280])
    routing_kernel<<<392, 256>>>(W_digit, 2);
    reduce_s_kernel<<<5, 256>>>();
    squash_v_kernel<<<1, 96>>>(out);

    // decoder
    fc1_kernel<<<8, 512>>>(target, fc1_w, fc1_b);
    fc2_kernel<<<8, 1024>>>(fc2_w, fc2_b);
    fc3_kernel<<<dim3(6, 8), 256>>>(fc3_w, fc3_b);
    upsample_kernel<<<162, 256>>>(out);
}

// round 4
// speedup vs baseline: 1.9997x; 1.2889x over previous
#include <cuda_runtime.h>
#include <math.h>
#include <stdint.h>

// ---------------- scratch (static __device__, no allocations) ----------------
__device__ float g_conv1[8 * 256 * 64 * 64];   // [b][oc][64*64]
__device__ float g_wpad[512 * 8192];           // pc1 weights tf32, K padded 25->32, frag-permuted
__device__ float g_pc1[8 * 512 * 900];         // [b][oc][30*30]
__device__ float g_pc2[8 * 256 * 900];
__device__ float g_pc3[8 * 256 * 784];         // [b][oc][28*28]
__device__ float g_u[8 * 25088 * 8];           // squashed primary caps
__device__ float g_blog[8 * 25088 * 10];       // routing logits
__device__ float g_spart[392 * 1280];          // per-block partial s
__device__ float g_s[1280];
__device__ float g_v[1280];
__device__ float g_h1[8 * 512];
__device__ float g_h2[8 * 1024];
__device__ float g_rec[8 * 1296];

__device__ __forceinline__ uint32_t f2tf32(float x) {
    uint32_t t;
    asm("cvt.rna.tf32.f32 %0, %1;" : "=r"(t) : "f"(x));
    return t;
}
__device__ __forceinline__ void mma_tf32_16x8x8(float* d, const uint32_t* a,
                                                const uint32_t* bfr) {
    asm volatile(
        "mma.sync.aligned.m16n8k8.row.col.f32.tf32.tf32.f32 "
        "{%0,%1,%2,%3}, {%4,%5,%6,%7}, {%8,%9}, {%0,%1,%2,%3};"
        : "+f"(d[0]), "+f"(d[1]), "+f"(d[2]), "+f"(d[3])
        : "r"(a[0]), "r"(a[1]), "r"(a[2]), "r"(a[3]), "r"(bfr[0]), "r"(bfr[1]));
}

// ---------------- conv1: 1->256ch, 9x9, relu ----------------
__global__ void conv1_kernel(const float* __restrict__ x,
                             const float* __restrict__ w,
                             const float* __restrict__ bias,
                             float* __restrict__ out) {
    int oc = blockIdx.x, b = blockIdx.y;
    __shared__ float xs[72 * 72];
    __shared__ float wsh[81];
    for (int i = threadIdx.x; i < 5184; i += 256) xs[i] = x[b * 5184 + i];
    if (threadIdx.x < 81) wsh[threadIdx.x] = w[oc * 81 + threadIdx.x];
    __syncthreads();
    float bv = bias[oc];
    for (int i = threadIdx.x; i < 4096; i += 256) {
        int oh = i >> 6, ow = i & 63;
        float acc = bv;
#pragma unroll
        for (int kh = 0; kh < 9; kh++)
#pragma unroll
            for (int kw = 0; kw < 9; kw++)
                acc += xs[(oh + kh) * 72 + ow + kw] * wsh[kh * 9 + kw];
        out[(b * 256 + oc) * 4096 + i] = fmaxf(acc, 0.f);
    }
}

// ---------------- pc1 weight prep: pad 25->32, permute k within 8, cvt tf32 ----------------
// layout: wp[oc][ic*32 + k8*8 + kp], element = w[oc][ic*25 + k8*8 + korig(kp)]
// korig(kp) = (kp>>1) + 4*(kp&1)   (so lds.64 pairs give (c, c+4))
__global__ void wpad_kernel(const float* __restrict__ w, float* __restrict__ wp) {
    int idx = blockIdx.x * 256 + threadIdx.x;
    if (idx >= 512 * 8192) return;
    int oc = idx >> 13, r = idx & 8191, ic = r >> 5, k = r & 31;
    int k8 = k >> 3, kp = k & 7;
    int ko = (kp >> 1) + 4 * (kp & 1);
    int e = k8 * 8 + ko;
    float v = (e < 25) ? w[oc * 6400 + ic * 25 + e] : 0.f;
    wp[idx] = __uint_as_float(f2tf32(v));
}

// ---------------- pc1 via mma.sync tf32: C[512oc,900sp] = W[512,8192] * im2col ----------------
// block 256 thr = 8 warps; tile 128oc x 128sp; warp = 32oc x 64sp; K-chunk 32 (1 ic)
#define KP 1032  // k8 section stride in floats (128*8 + 8 pad -> conflict-free STS)
__global__ void __launch_bounds__(256, 2)
pc1_mma_kernel(const float* __restrict__ in, const float4* __restrict__ wpad4,
               const float* __restrict__ bias, float* __restrict__ out) {
    __shared__ float As[4 * KP];
    __shared__ float Bs[4 * KP];
    const int tid = threadIdx.x;
    const int lane = tid & 31, wid = tid >> 5;
    const int spt = blockIdx.x, oct = blockIdx.y, b = blockIdx.z;
    const int oc_base = oct * 128, sp_base = spt * 128;
    const int wm = wid & 3, wn = wid >> 2;

    // producer geometry
    const int rr = tid >> 3, grp = tid & 7;
    const int k8p = grp >> 1, half = grp & 1;
    int eoff[4], eok[4];
    {
        const int kos0[4] = {0, 4, 1, 5};
        const int kos1[4] = {2, 6, 3, 7};
#pragma unroll
        for (int t = 0; t < 4; t++) {
            int e = k8p * 8 + (half ? kos1[t] : kos0[t]);
            eok[t] = (e < 25);
            int eh = e / 5, ew = e - eh * 5;
            eoff[t] = eh * 64 + ew;
        }
    }
    int p0[4], bval[4];
#pragma unroll
    for (int q = 0; q < 4; q++) {
        int sp = sp_base + 32 * q + rr;
        bval[q] = (sp < 900);
        int oh = bval[q] ? sp / 30 : 0;
        int ow = bval[q] ? sp - oh * 30 : 0;
        p0[q] = oh * 128 + ow * 2;
    }
    const float* inb = in + (size_t)b * 256 * 4096;

    float acc[2][8][4];
#pragma unroll
    for (int mt = 0; mt < 2; mt++)
#pragma unroll
        for (int nt = 0; nt < 8; nt++)
#pragma unroll
            for (int i = 0; i < 4; i++) acc[mt][nt][i] = 0.f;

    const int gr = lane >> 2;        // fragment row group 0..7
    const int gc2 = (lane & 3) * 2;  // permuted col pair offset

    for (int ic = 0; ic < 256; ic++) {
        __syncthreads();
        // A tile: 128oc x 32k (already tf32 + permuted in gmem)
#pragma unroll
        for (int q = 0; q < 4; q++) {
            float4 av = wpad4[(size_t)(oc_base + 32 * q + rr) * 2048 + ic * 8 + grp];
            *(float4*)&As[k8p * KP + (32 * q + rr) * 8 + half * 4] = av;
        }
        // B tile: im2col gather + tf32 round
#pragma unroll
        for (int q = 0; q < 4; q++) {
            uint32_t v0 = 0, v1 = 0, v2 = 0, v3 = 0;
            if (bval[q]) {
                const float* ip = inb + ic * 4096 + p0[q];
                if (eok[0]) v0 = f2tf32(ip[eoff[0]]);
                if (eok[1]) v1 = f2tf32(ip[eoff[1]]);
                if (eok[2]) v2 = f2tf32(ip[eoff[2]]);
                if (eok[3]) v3 = f2tf32(ip[eoff[3]]);
            }
            *(float4*)&Bs[k8p * KP + (32 * q + rr) * 8 + half * 4] =
                make_float4(__uint_as_float(v0), __uint_as_float(v1),
                            __uint_as_float(v2), __uint_as_float(v3));
        }
        __syncthreads();
#pragma unroll
        for (int k8 = 0; k8 < 4; k8++) {
            uint32_t afr[2][4];
#pragma unroll
            for (int mt = 0; mt < 2; mt++) {
                int mrow = (wm * 2 + mt) * 16 + gr;
                float2 lo = *(const float2*)&As[k8 * KP + mrow * 8 + gc2];
                float2 hi = *(const float2*)&As[k8 * KP + (mrow + 8) * 8 + gc2];
                afr[mt][0] = __float_as_uint(lo.x);
                afr[mt][1] = __float_as_uint(hi.x);
                afr[mt][2] = __float_as_uint(lo.y);
                afr[mt][3] = __float_as_uint(hi.y);
            }
#pragma unroll
            for (int nt = 0; nt < 8; nt++) {
                int n = (wn * 8 + nt) * 8 + gr;
                float2 bf = *(const float2*)&Bs[k8 * KP + n * 8 + gc2];
                uint32_t bfr[2] = {__float_as_uint(bf.x), __float_as_uint(bf.y)};
                mma_tf32_16x8x8(acc[0][nt], afr[0], bfr);
                mma_tf32_16x8x8(acc[1][nt], afr[1], bfr);
            }
        }
    }
    // epilogue
#pragma unroll
    for (int mt = 0; mt < 2; mt++) {
        int oc0 = oc_base + (wm * 2 + mt) * 16 + gr;
        float b0 = bias[oc0], b1 = bias[oc0 + 8];
        float* op0 = out + ((size_t)b * 512 + oc0) * 900;
        float* op1 = out + ((size_t)b * 512 + oc0 + 8) * 900;
#pragma unroll
        for (int nt = 0; nt < 8; nt++) {
            int sp = sp_base + (wn * 8 + nt) * 8 + gc2;
            if (sp < 900) {
                *(float2*)&op0[sp] = make_float2(acc[mt][nt][0] + b0, acc[mt][nt][1] + b0);
                *(float2*)&op1[sp] = make_float2(acc[mt][nt][2] + b1, acc[mt][nt][3] + b1);
            }
        }
    }
}

// ---------------- pc2: grouped 32g, 16->8, 3x3, pad 1 (2 spatial halves) ----------------
__global__ void pc2_kernel(const float* __restrict__ in,
                           const float* __restrict__ w,
                           const float* __restrict__ bias,
                           float* __restrict__ out) {
    int g = blockIdx.x, b = blockIdx.y, half = blockIdx.z;
    int oh0 = half * 15;
    __shared__ float wsh[1152];
    __shared__ float xin[16 * 17 * 30];
    for (int idx = threadIdx.x; idx < 1152; idx += 256) wsh[idx] = w[g * 1152 + idx];
    const float* inb = in + ((size_t)b * 512 + g * 16) * 900;
    for (int idx = threadIdx.x; idx < 8160; idx += 256) {
        int iw = idx % 30;
        int r2 = idx / 30;
        int ihl = r2 % 17, i = r2 / 17;
        int ih = oh0 - 1 + ihl;
        xin[idx] = (ih >= 0 && ih < 30) ? inb[i * 900 + ih * 30 + iw] : 0.f;
    }
    __syncthreads();
    for (int spl = threadIdx.x; spl < 450; spl += 256) {
        int ohl = spl / 30, ow = spl - ohl * 30;
        int oh = oh0 + ohl;
        float acc[8];
#pragma unroll
        for (int o = 0; o < 8; o++) acc[o] = bias[g * 8 + o];
        for (int i = 0; i < 16; i++) {
            const float* ip = xin + i * 510;
#pragma unroll
            for (int kh = 0; kh < 3; kh++) {
#pragma unroll
                for (int kw = 0; kw < 3; kw++) {
                    int iw = ow - 1 + kw;
                    if (iw < 0 || iw >= 30) continue;
                    float v = ip[(ohl + kh) * 30 + iw];
                    int e = kh * 3 + kw;
#pragma unroll
                    for (int o = 0; o < 8; o++) acc[o] += v * wsh[(o * 16 + i) * 9 + e];
                }
            }
        }
#pragma unroll
        for (int o = 0; o < 8; o++)
            out[((size_t)b * 256 + g * 8 + o) * 900 + oh * 30 + ow] = acc[o];
    }
}

// ---------------- pc3: grouped 32g, 8->8, 3x3, pad 0 (30->28), 2 halves ----------------
__global__ void pc3_kernel(const float* __restrict__ in,
                           const float* __restrict__ w,
                           const float* __restrict__ bias,
                           float* __restrict__ out) {
    int g = blockIdx.x, b = blockIdx.y, half = blockIdx.z;
    int oh0 = half * 14;
    __shared__ float wsh[576];
    __shared__ float xin[8 * 16 * 30];
    for (int idx = threadIdx.x; idx < 576; idx += 256) wsh[idx] = w[g * 576 + idx];
    const float* inb = in + ((size_t)b * 256 + g * 8) * 900;
    for (int idx = threadIdx.x; idx < 3840; idx += 256) {
        int iw = idx % 30;
        int r2 = idx / 30;
        int ihl = r2 % 16, i = r2 / 16;
        xin[idx] = inb[i * 900 + (oh0 + ihl) * 30 + iw];
    }
    __syncthreads();
    for (int spl = threadIdx.x; spl < 392; spl += 256) {
        int ohl = spl / 28, ow = spl - ohl * 28;
        int oh = oh0 + ohl;
        float acc[8];
#pragma unroll
        for (int o = 0; o < 8; o++) acc[o] = bias[g * 8 + o];
        for (int i = 0; i < 8; i++) {
            const float* ip = xin + i * 480;
#pragma unroll
            for (int kh = 0; kh < 3; kh++) {
#pragma unroll
                for (int kw = 0; kw < 3; kw++) {
                    float v = ip[(ohl + kh) * 30 + ow + kw];
                    int e = kh * 3 + kw;
#pragma unroll
                    for (int o = 0; o < 8; o++) acc[o] += v * wsh[(o * 8 + i) * 9 + e];
                }
            }
        }
#pragma unroll
        for (int o = 0; o < 8; o++)
            out[((size_t)b * 256 + g * 8 + o) * 784 + oh * 28 + ow] = acc[o];
    }
}

// ---------------- build u (capsule transpose) + squash over dim 8 ----------------
__global__ void u_build_kernel(const float* __restrict__ y, float* __restrict__ u) {
    int b = blockIdx.y;
    int s0 = blockIdx.x * 16;
    __shared__ float ys[256 * 16];
    for (int i = threadIdx.x; i < 4096; i += 256) {
        int ch = i >> 4, si = i & 15;
        ys[i] = y[(b * 256 + ch) * 784 + s0 + si];
    }
    __syncthreads();
    for (int p = threadIdx.x; p < 512; p += 256) {
        int si = p >> 5, cap = p & 31;
        float d[8];
        float sq = 0.f;
#pragma unroll
        for (int i = 0; i < 8; i++) {
            d[i] = ys[(cap * 8 + i) * 16 + si];
            sq += d[i] * d[i];
        }
        float f = sq / (sqrtf(sq) * (1.f + sq));
        int n = (s0 + si) * 32 + cap;
        float* up = u + ((size_t)b * 25088 + n) * 8;
#pragma unroll
        for (int i = 0; i < 8; i++) up[i] = f * d[i];
    }
}

// ---------------- fused routing pass ----------------
__global__ void routing_kernel(const float* __restrict__ W, int mode) {
    int warp = (blockIdx.x * 256 + threadIdx.x) >> 5;
    int lane = threadIdx.x & 31;
    int bhalf = lane >> 4;
    int j = lane & 15;
    float s_acc[4][10];
#pragma unroll
    for (int bp = 0; bp < 4; bp++)
#pragma unroll
        for (int k = 0; k < 10; k++) s_acc[bp][k] = 0.f;

    int n0 = warp * 8;
    for (int nn = 0; nn < 8; nn++) {
        int n = n0 + nn;
        const float* Wn = W + (size_t)n * 1280;
#pragma unroll
        for (int bp = 0; bp < 4; bp++) {
            int b = bp * 2 + bhalf;
            const float* up = g_u + ((size_t)b * 25088 + n) * 8;
            float uu[8];
#pragma unroll
            for (int i = 0; i < 8; i++) uu[i] = up[i];
            float uh[10];
#pragma unroll
            for (int k = 0; k < 10; k++) {
                float a = 0.f;
#pragma unroll
                for (int i = 0; i < 8; i++) a += uu[i] * Wn[k * 128 + i * 16 + j];
                uh[k] = a;
            }
            float c[10];
            if (mode == 0) {
#pragma unroll
                for (int k = 0; k < 10; k++) c[k] = 0.1f;
            } else {
                float bl[10];
#pragma unroll
                for (int k = 0; k < 10; k++) {
                    float d = uh[k] * g_v[(b * 10 + k) * 16 + j];
                    d += __shfl_xor_sync(0xffffffffu, d, 1);
                    d += __shfl_xor_sync(0xffffffffu, d, 2);
                    d += __shfl_xor_sync(0xffffffffu, d, 4);
                    d += __shfl_xor_sync(0xffffffffu, d, 8);
                    bl[k] = d;
                }
                if (mode == 2) {
#pragma unroll
                    for (int k = 0; k < 10; k++)
                        bl[k] += g_blog[((size_t)b * 25088 + n) * 10 + k];
                } else if (j == 0) {
#pragma unroll
                    for (int k = 0; k < 10; k++)
                        g_blog[((size_t)b * 25088 + n) * 10 + k] = bl[k];
                }
                float m = bl[0];
#pragma unroll
                for (int k = 1; k < 10; k++) m = fmaxf(m, bl[k]);
                float sum = 0.f;
#pragma unroll
                for (int k = 0; k < 10; k++) { c[k] = expf(bl[k] - m); sum += c[k]; }
                float inv = 1.f / sum;
#pragma unroll
                for (int k = 0; k < 10; k++) c[k] *= inv;
            }
#pragma unroll
            for (int k = 0; k < 10; k++) s_acc[bp][k] += c[k] * uh[k];
        }
    }
    __shared__ float ssm[8][1280];
    int wl = (threadIdx.x >> 5);
#pragma unroll
    for (int bp = 0; bp < 4; bp++) {
        int b = bp * 2 + bhalf;
#pragma unroll
        for (int k = 0; k < 10; k++)
            ssm[wl][(b * 10 + k) * 16 + j] = s_acc[bp][k];
    }
    __syncthreads();
    for (int i = threadIdx.x; i < 1280; i += 256) {
        float t = 0.f;
#pragma unroll
        for (int w = 0; w < 8; w++) t += ssm[w][i];
        g_spart[blockIdx.x * 1280 + i] = t;
    }
}

__global__ void reduce_s_kernel() {
    int i = blockIdx.x * 256 + threadIdx.x;
    if (i < 1280) {
        float t = 0.f;
        for (int p = 0; p < 392; p++) t += g_spart[p * 1280 + i];
        g_s[i] = t;
    }
}

__global__ void squash_v_kernel(float* out_opt) {
    int t = threadIdx.x;
    if (t < 80) {
        int base = t * 16;
        float sv[16];
        float sq = 0.f;
#pragma unroll
        for (int jj = 0; jj < 16; jj++) { sv[jj] = g_s[base + jj]; sq += sv[jj] * sv[jj]; }
        float f = sq / (sqrtf(sq) * (1.f + sq));
#pragma unroll
        for (int jj = 0; jj < 16; jj++) {
            float vv = f * sv[jj];
            g_v[base + jj] = vv;
            if (out_opt) out_opt[base + jj] = vv;
        }
    }
}

// ---------------- decoder ----------------
__global__ void fc1_kernel(const float* __restrict__ target,
                           const float* __restrict__ w,
                           const float* __restrict__ bias) {
    int b = blockIdx.x;
    __shared__ float vm[16];
    if (threadIdx.x < 16) {
        float a = 0.f;
        for (int k = 0; k < 10; k++) a += target[b * 10 + k] * g_v[(b * 10 + k) * 16 + threadIdx.x];
        vm[threadIdx.x] = a;
    }
    __syncthreads();
    int o = threadIdx.x;
    float acc = bias[o];
#pragma unroll
    for (int i = 0; i < 16; i++) acc += vm[i] * w[o * 16 + i];
    g_h1[b * 512 + o] = fmaxf(acc, 0.f);
}

__global__ void fc2_kernel(const float* __restrict__ w, const float* __restrict__ bias) {
    int b = blockIdx.x;
    __shared__ float h1[512];
    if (threadIdx.x < 512) h1[threadIdx.x] = g_h1[b * 512 + threadIdx.x];
    __syncthreads();
    int o = threadIdx.x;
    float acc = bias[o];
    for (int i = 0; i < 512; i++) acc += h1[i] * w[o * 512 + i];
    g_h2[b * 1024 + o] = fmaxf(acc, 0.f);
}

__global__ void fc3_kernel(const float* __restrict__ w, const float* __restrict__ bias) {
    int b = blockIdx.y;
    int o = blockIdx.x * 256 + threadIdx.x;
    __shared__ float h2[1024];
    for (int i = threadIdx.x; i < 1024; i += 256) h2[i] = g_h2[b * 1024 + i];
    __syncthreads();
    if (o < 1296) {
        float acc = bias[o];
        for (int i = 0; i < 1024; i++) acc += h2[i] * w[o * 1024 + i];
        g_rec[b * 1296 + o] = 1.f / (1.f + expf(-acc));
    }
}

__global__ void upsample_kernel(float* __restrict__ out) {
    int idx = blockIdx.x * 256 + threadIdx.x;
    if (idx >= 8 * 5184) return;
    int b = idx / 5184;
    int r = idx - b * 5184;
    int oy = r / 72, ox = r - oy * 72;
    float sy = (float)(oy * 35) / 71.0f;
    float sx = (float)(ox * 35) / 71.0f;
    int y0 = (int)sy, x0 = (int)sx;
    int y1 = min(y0 + 1, 35), x1 = min(x0 + 1, 35);
    float wy = sy - (float)y0, wx = sx - (float)x0;
    const float* rb = g_rec + b * 1296;
    float a00 = rb[y0 * 36 + x0], a01 = rb[y0 * 36 + x1];
    float a10 = rb[y1 * 36 + x0], a11 = rb[y1 * 36 + x1];
    float v = (1.f - wy) * ((1.f - wx) * a00 + wx * a01) +
              wy * ((1.f - wx) * a10 + wx * a11);
    out[1280 + b * 5184 + r] = v;
}

// ---------------- launch ----------------
extern "C" void kernel_launch(void* const* d_in, const int* in_sizes, int n_in,
                              void* d_out, int out_size) {
    const float* x       = (const float*)d_in[0];
    const float* target  = (const float*)d_in[1];
    const float* conv1_w = (const float*)d_in[2];
    const float* conv1_b = (const float*)d_in[3];
    const float* pc1_w   = (const float*)d_in[4];
    const float* pc1_b   = (const float*)d_in[5];
    const float* pc2_w   = (const float*)d_in[6];
    const float* pc2_b   = (const float*)d_in[7];
    const float* pc3_w   = (const float*)d_in[8];
    const float* pc3_b   = (const float*)d_in[9];
    const float* W_digit = (const float*)d_in[10];
    const float* fc1_w   = (const float*)d_in[11];
    const float* fc1_b   = (const float*)d_in[12];
    const float* fc2_w   = (const float*)d_in[13];
    const float* fc2_b   = (const float*)d_in[14];
    const float* fc3_w   = (const float*)d_in[15];
    const float* fc3_b   = (const float*)d_in[16];
    float* out = (float*)d_out;

    float *conv1p, *wpp, *pc1p, *pc2p, *pc3p, *up;
    cudaGetSymbolAddress((void**)&conv1p, g_conv1);
    cudaGetSymbolAddress((void**)&wpp, g_wpad);
    cudaGetSymbolAddress((void**)&pc1p, g_pc1);
    cudaGetSymbolAddress((void**)&pc2p, g_pc2);
    cudaGetSymbolAddress((void**)&pc3p, g_pc3);
    cudaGetSymbolAddress((void**)&up, g_u);

    conv1_kernel<<<dim3(256, 8), 256>>>(x, conv1_w, conv1_b, conv1p);
    wpad_kernel<<<16384, 256>>>(pc1_w, wpp);
    pc1_mma_kernel<<<dim3(8, 4, 8), 256>>>(conv1p, (const float4*)wpp, pc1_b, pc1p);
    pc2_kernel<<<dim3(32, 8, 2), 256>>>(pc1p, pc2_w, pc2_b, pc2p);
    pc3_kernel<<<dim3(32, 8, 2), 256>>>(pc2p, pc3_w, pc3_b, pc3p);
    u_build_kernel<<<dim3(49, 8), 256>>>(pc3p, up);

    // routing iteration 1 (uniform c)
    routing_kernel<<<392, 256>>>(W_digit, 0);
    reduce_s_kernel<<<5, 256>>>();
    squash_v_kernel<<<1, 96>>>(nullptr);
    // routing iteration 2
    routing_kernel<<<392, 256>>>(W_digit, 1);
    reduce_s_kernel<<<5, 256>>>();
    squash_v_kernel<<<1, 96>>>(nullptr);
    // routing iteration 3 (final v -> d_out[0:1280])
    routing_kernel<<<392, 256>>>(W_digit, 2);
    reduce_s_kernel<<<5, 256>>>();
    squash_v_kernel<<<1, 96>>>(out);

    // decoder
    fc1_kernel<<<8, 512>>>(target, fc1_w, fc1_b);
    fc2_kernel<<<8, 1024>>>(fc2_w, fc2_b);
    fc3_kernel<<<dim3(6, 8), 256>>>(fc3_w, fc3_b);
    upsample_kernel<<<162, 256>>>(out);
}

// round 6
// speedup vs baseline: 2.5047x; 1.2526x over previous
#include <cuda_runtime.h>
#include <cuda_fp16.h>
#include <math.h>
#include <stdint.h>

// ---------------- scratch (static __device__, no allocations) ----------------
__device__ float g_conv1[8 * 256 * 64 * 64];   // [b][oc][64*64]
__device__ __half g_wpadh[512 * 8192];         // pc1 weights fp16, K padded 25->32
__device__ float g_pc1[8 * 512 * 900];         // [b][oc][30*30]
__device__ float g_pc2[8 * 256 * 900];
__device__ float g_pc3[8 * 256 * 784];         // [b][oc][28*28]
__device__ float g_u[8 * 25088 * 8];           // squashed primary caps
__device__ float g_blog[8 * 25088 * 10];       // routing logits
__device__ float g_spart[392 * 1280];          // per-block partial s
__device__ float g_s[1280];
__device__ float g_v[1280];
__device__ float g_h1[8 * 512];
__device__ float g_h2[8 * 1024];
__device__ float g_rec[8 * 1296];

__device__ __forceinline__ void mma_fp16_16x8x16(float* d, const uint32_t* a,
                                                 uint32_t b0, uint32_t b1) {
    asm volatile(
        "mma.sync.aligned.m16n8k16.row.col.f32.f16.f16.f32 "
        "{%0,%1,%2,%3}, {%4,%5,%6,%7}, {%8,%9}, {%0,%1,%2,%3};"
        : "+f"(d[0]), "+f"(d[1]), "+f"(d[2]), "+f"(d[3])
        : "r"(a[0]), "r"(a[1]), "r"(a[2]), "r"(a[3]), "r"(b0), "r"(b1));
}

// ---------------- conv1: 1->256ch, 9x9, relu ----------------
__global__ void conv1_kernel(const float* __restrict__ x,
                             const float* __restrict__ w,
                             const float* __restrict__ bias,
                             float* __restrict__ out) {
    int oc = blockIdx.x, b = blockIdx.y;
    __shared__ float xs[72 * 72];
    __shared__ float wsh[81];
    for (int i = threadIdx.x; i < 5184; i += 256) xs[i] = x[b * 5184 + i];
    if (threadIdx.x < 81) wsh[threadIdx.x] = w[oc * 81 + threadIdx.x];
    __syncthreads();
    float bv = bias[oc];
    for (int i = threadIdx.x; i < 4096; i += 256) {
        int oh = i >> 6, ow = i & 63;
        float acc = bv;
#pragma unroll
        for (int kh = 0; kh < 9; kh++)
#pragma unroll
            for (int kw = 0; kw < 9; kw++)
                acc += xs[(oh + kh) * 72 + ow + kw] * wsh[kh * 9 + kw];
        out[(b * 256 + oc) * 4096 + i] = fmaxf(acc, 0.f);
    }
}

// ---------------- pc1 weight prep: pad 25->32, cvt fp16 (natural k order) ----------------
__global__ void wpad_kernel(const float* __restrict__ w, __half* __restrict__ wp) {
    int idx = blockIdx.x * 256 + threadIdx.x;
    if (idx >= 512 * 8192) return;
    int oc = idx >> 13, r = idx & 8191, ic = r >> 5, k = r & 31;
    float v = (k < 25) ? w[oc * 6400 + ic * 25 + k] : 0.f;
    wp[idx] = __float2half(v);
}

// ---------------- pc1 via mma.sync fp16 m16n8k16 ----------------
// block 256 thr = 8 warps; tile 128oc x 128sp; warp = 32oc x 64sp; K-chunk 32 (1 ic)
#define ASTR 40  // halves per row (80B) -> conflict-free fragment reads
__global__ void __launch_bounds__(256, 2)
pc1_mma_kernel(const float* __restrict__ in, const uint2* __restrict__ wph2,
               const float* __restrict__ bias, float* __restrict__ out) {
    __shared__ __half As[128 * ASTR];
    __shared__ __half Bs[128 * ASTR];
    const int tid = threadIdx.x;
    const int lane = tid & 31, wid = tid >> 5;
    const int spt = blockIdx.x, oct = blockIdx.y, b = blockIdx.z;
    const int oc_base = oct * 128, sp_base = spt * 128;
    const int wm = wid & 3, wn = wid >> 2;

    // producer geometry: thread (rr 0..31, grp 0..7) covers row 32q+rr, k = grp*4..grp*4+3
    const int rr = tid >> 3, grp = tid & 7;
    int eoff[4], eok[4];
#pragma unroll
    for (int t = 0; t < 4; t++) {
        int e = grp * 4 + t;
        eok[t] = (e < 25);
        int eh = e / 5, ew = e - eh * 5;
        eoff[t] = eh * 64 + ew;
    }
    int p0[4], bval[4];
#pragma unroll
    for (int q = 0; q < 4; q++) {
        int sp = sp_base + 32 * q + rr;
        bval[q] = (sp < 900);
        int oh = bval[q] ? sp / 30 : 0;
        int ow = bval[q] ? sp - oh * 30 : 0;
        p0[q] = oh * 128 + ow * 2;
    }
    const float* inb = in + (size_t)b * 256 * 4096;

    float acc[2][8][4];
#pragma unroll
    for (int mt = 0; mt < 2; mt++)
#pragma unroll
        for (int nt = 0; nt < 8; nt++)
#pragma unroll
            for (int i = 0; i < 4; i++) acc[mt][nt][i] = 0.f;

    const int gr = lane >> 2;        // fragment row/col group 0..7
    const int c2 = (lane & 3) * 2;   // k pair offset

    for (int ic = 0; ic < 256; ic++) {
        __syncthreads();
        // A tile: 128oc x 32k halves (coalesced 8B loads)
#pragma unroll
        for (int q = 0; q < 4; q++) {
            uint2 av = wph2[(size_t)(oc_base + 32 * q + rr) * 2048 + ic * 8 + grp];
            *(uint2*)&As[(32 * q + rr) * ASTR + grp * 4] = av;
        }
        // B tile: im2col gather + fp16 convert
#pragma unroll
        for (int q = 0; q < 4; q++) {
            float f0 = 0.f, f1 = 0.f, f2 = 0.f, f3 = 0.f;
            if (bval[q]) {
                const float* ip = inb + ic * 4096 + p0[q];
                if (eok[0]) f0 = ip[eoff[0]];
                if (eok[1]) f1 = ip[eoff[1]];
                if (eok[2]) f2 = ip[eoff[2]];
                if (eok[3]) f3 = ip[eoff[3]];
            }
            __half2 h01 = __floats2half2_rn(f0, f1);
            __half2 h23 = __floats2half2_rn(f2, f3);
            uint2 bv;
            bv.x = *(uint32_t*)&h01;
            bv.y = *(uint32_t*)&h23;
            *(uint2*)&Bs[(32 * q + rr) * ASTR + grp * 4] = bv;
        }
        __syncthreads();
#pragma unroll
        for (int k16 = 0; k16 < 2; k16++) {
            int kb = k16 * 16 + c2;
            uint32_t afr[2][4];
#pragma unroll
            for (int mt = 0; mt < 2; mt++) {
                int r0 = (wm * 2 + mt) * 16 + gr;
                afr[mt][0] = *(const uint32_t*)&As[r0 * ASTR + kb];
                afr[mt][1] = *(const uint32_t*)&As[(r0 + 8) * ASTR + kb];
                afr[mt][2] = *(const uint32_t*)&As[r0 * ASTR + kb + 8];
                afr[mt][3] = *(const uint32_t*)&As[(r0 + 8) * ASTR + kb + 8];
            }
#pragma unroll
            for (int nt = 0; nt < 8; nt++) {
                int n = (wn * 8 + nt) * 8 + gr;
                uint32_t b0 = *(const uint32_t*)&Bs[n * ASTR + kb];
                uint32_t b1 = *(const uint32_t*)&Bs[n * ASTR + kb + 8];
                mma_fp16_16x8x16(acc[0][nt], afr[0], b0, b1);
                mma_fp16_16x8x16(acc[1][nt], afr[1], b0, b1);
            }
        }
    }
    // epilogue: acc[mt][nt] = rows {gr, gr+8} of 16-row group, cols c2..c2+1 of 8-col group
#pragma unroll
    for (int mt = 0; mt < 2; mt++) {
        int oc0 = oc_base + (wm * 2 + mt) * 16 + gr;
        float b0 = bias[oc0], b1 = bias[oc0 + 8];
        float* op0 = out + ((size_t)b * 512 + oc0) * 900;
        float* op1 = out + ((size_t)b * 512 + oc0 + 8) * 900;
#pragma unroll
        for (int nt = 0; nt < 8; nt++) {
            int sp = sp_base + (wn * 8 + nt) * 8 + c2;
            if (sp < 900) {
                *(float2*)&op0[sp] = make_float2(acc[mt][nt][0] + b0, acc[mt][nt][1] + b0);
                *(float2*)&op1[sp] = make_float2(acc[mt][nt][2] + b1, acc[mt][nt][3] + b1);
            }
        }
    }
}

// ---------------- pc2: grouped 32g, 16->8, 3x3, pad 1 (2 spatial halves) ----------------
__global__ void pc2_kernel(const float* __restrict__ in,
                           const float* __restrict__ w,
                           const float* __restrict__ bias,
                           float* __restrict__ out) {
    int g = blockIdx.x, b = blockIdx.y, half = blockIdx.z;
    int oh0 = half * 15;
    __shared__ float wsh[1152];
    __shared__ float xin[16 * 17 * 30];
    for (int idx = threadIdx.x; idx < 1152; idx += 256) wsh[idx] = w[g * 1152 + idx];
    const float* inb = in + ((size_t)b * 512 + g * 16) * 900;
    for (int idx = threadIdx.x; idx < 8160; idx += 256) {
        int iw = idx % 30;
        int r2 = idx / 30;
        int ihl = r2 % 17, i = r2 / 17;
        int ih = oh0 - 1 + ihl;
        xin[idx] = (ih >= 0 && ih < 30) ? inb[i * 900 + ih * 30 + iw] : 0.f;
    }
    __syncthreads();
    for (int spl = threadIdx.x; spl < 450; spl += 256) {
        int ohl = spl / 30, ow = spl - ohl * 30;
        int oh = oh0 + ohl;
        float acc[8];
#pragma unroll
        for (int o = 0; o < 8; o++) acc[o] = bias[g * 8 + o];
        for (int i = 0; i < 16; i++) {
            const float* ip = xin + i * 510;
#pragma unroll
            for (int kh = 0; kh < 3; kh++) {
#pragma unroll
                for (int kw = 0; kw < 3; kw++) {
                    int iw = ow - 1 + kw;
                    if (iw < 0 || iw >= 30) continue;
                    float v = ip[(ohl + kh) * 30 + iw];
                    int e = kh * 3 + kw;
#pragma unroll
                    for (int o = 0; o < 8; o++) acc[o] += v * wsh[(o * 16 + i) * 9 + e];
                }
            }
        }
#pragma unroll
        for (int o = 0; o < 8; o++)
            out[((size_t)b * 256 + g * 8 + o) * 900 + oh * 30 + ow] = acc[o];
    }
}

// ---------------- pc3: grouped 32g, 8->8, 3x3, pad 0 (30->28), 2 halves ----------------
__global__ void pc3_kernel(const float* __restrict__ in,
                           const float* __restrict__ w,
                           const float* __restrict__ bias,
                           float* __restrict__ out) {
    int g = blockIdx.x, b = blockIdx.y, half = blockIdx.z;
    int oh0 = half * 14;
    __shared__ float wsh[576];
    __shared__ float xin[8 * 16 * 30];
    for (int idx = threadIdx.x; idx < 576; idx += 256) wsh[idx] = w[g * 576 + idx];
    const float* inb = in + ((size_t)b * 256 + g * 8) * 900;
    for (int idx = threadIdx.x; idx < 3840; idx += 256) {
        int iw = idx % 30;
        int r2 = idx / 30;
        int ihl = r2 % 16, i = r2 / 16;
        xin[idx] = inb[i * 900 + (oh0 + ihl) * 30 + iw];
    }
    __syncthreads();
    for (int spl = threadIdx.x; spl < 392; spl += 256) {
        int ohl = spl / 28, ow = spl - ohl * 28;
        int oh = oh0 + ohl;
        float acc[8];
#pragma unroll
        for (int o = 0; o < 8; o++) acc[o] = bias[g * 8 + o];
        for (int i = 0; i < 8; i++) {
            const float* ip = xin + i * 480;
#pragma unroll
            for (int kh = 0; kh < 3; kh++) {
#pragma unroll
                for (int kw = 0; kw < 3; kw++) {
                    float v = ip[(ohl + kh) * 30 + ow + kw];
                    int e = kh * 3 + kw;
#pragma unroll
                    for (int o = 0; o < 8; o++) acc[o] += v * wsh[(o * 8 + i) * 9 + e];
                }
            }
        }
#pragma unroll
        for (int o = 0; o < 8; o++)
            out[((size_t)b * 256 + g * 8 + o) * 784 + oh * 28 + ow] = acc[o];
    }
}

// ---------------- build u (capsule transpose) + squash over dim 8 ----------------
__global__ void u_build_kernel(const float* __restrict__ y, float* __restrict__ u) {
    int b = blockIdx.y;
    int s0 = blockIdx.x * 16;
    __shared__ float ys[256 * 16];
    for (int i = threadIdx.x; i < 4096; i += 256) {
        int ch = i >> 4, si = i & 15;
        ys[i] = y[(b * 256 + ch) * 784 + s0 + si];
    }
    __syncthreads();
    for (int p = threadIdx.x; p < 512; p += 256) {
        int si = p >> 5, cap = p & 31;
        float d[8];
        float sq = 0.f;
#pragma unroll
        for (int i = 0; i < 8; i++) {
            d[i] = ys[(cap * 8 + i) * 16 + si];
            sq += d[i] * d[i];
        }
        float f = sq / (sqrtf(sq) * (1.f + sq));
        int n = (s0 + si) * 32 + cap;
        float* up = u + ((size_t)b * 25088 + n) * 8;
#pragma unroll
        for (int i = 0; i < 8; i++) up[i] = f * d[i];
    }
}

// ---------------- fused routing pass ----------------
__global__ void routing_kernel(const float* __restrict__ W, int mode) {
    int warp = (blockIdx.x * 256 + threadIdx.x) >> 5;
    int lane = threadIdx.x & 31;
    int bhalf = lane >> 4;
    int j = lane & 15;
    float s_acc[4][10];
#pragma unroll
    for (int bp = 0; bp < 4; bp++)
#pragma unroll
        for (int k = 0; k < 10; k++) s_acc[bp][k] = 0.f;

    int n0 = warp * 8;
    for (int nn = 0; nn < 8; nn++) {
        int n = n0 + nn;
        const float* Wn = W + (size_t)n * 1280;
#pragma unroll
        for (int bp = 0; bp < 4; bp++) {
            int b = bp * 2 + bhalf;
            const float* up = g_u + ((size_t)b * 25088 + n) * 8;
            float uu[8];
#pragma unroll
            for (int i = 0; i < 8; i++) uu[i] = up[i];
            float uh[10];
#pragma unroll
            for (int k = 0; k < 10; k++) {
                float a = 0.f;
#pragma unroll
                for (int i = 0; i < 8; i++) a += uu[i] * Wn[k * 128 + i * 16 + j];
                uh[k] = a;
            }
            float c[10];
            if (mode == 0) {
#pragma unroll
                for (int k = 0; k < 10; k++) c[k] = 0.1f;
            } else {
                float bl[10];
#pragma unroll
                for (int k = 0; k < 10; k++) {
                    float d = uh[k] * g_v[(b * 10 + k) * 16 + j];
                    d += __shfl_xor_sync(0xffffffffu, d, 1);
                    d += __shfl_xor_sync(0xffffffffu, d, 2);
                    d += __shfl_xor_sync(0xffffffffu, d, 4);
                    d += __shfl_xor_sync(0xffffffffu, d, 8);
                    bl[k] = d;
                }
                if (mode == 2) {
#pragma unroll
                    for (int k = 0; k < 10; k++)
                        bl[k] += g_blog[((size_t)b * 25088 + n) * 10 + k];
                } else if (j == 0) {
#pragma unroll
                    for (int k = 0; k < 10; k++)
                        g_blog[((size_t)b * 25088 + n) * 10 + k] = bl[k];
                }
                float m = bl[0];
#pragma unroll
                for (int k = 1; k < 10; k++) m = fmaxf(m, bl[k]);
                float sum = 0.f;
#pragma unroll
                for (int k = 0; k < 10; k++) { c[k] = expf(bl[k] - m); sum += c[k]; }
                float inv = 1.f / sum;
#pragma unroll
                for (int k = 0; k < 10; k++) c[k] *= inv;
            }
#pragma unroll
            for (int k = 0; k < 10; k++) s_acc[bp][k] += c[k] * uh[k];
        }
    }
    __shared__ float ssm[8][1280];
    int wl = (threadIdx.x >> 5);
#pragma unroll
    for (int bp = 0; bp < 4; bp++) {
        int b = bp * 2 + bhalf;
#pragma unroll
        for (int k = 0; k < 10; k++)
            ssm[wl][(b * 10 + k) * 16 + j] = s_acc[bp][k];
    }
    __syncthreads();
    for (int i = threadIdx.x; i < 1280; i += 256) {
        float t = 0.f;
#pragma unroll
        for (int w = 0; w < 8; w++) t += ssm[w][i];
        g_spart[blockIdx.x * 1280 + i] = t;
    }
}

__global__ void reduce_s_kernel() {
    int i = blockIdx.x * 256 + threadIdx.x;
    if (i < 1280) {
        float t = 0.f;
        for (int p = 0; p < 392; p++) t += g_spart[p * 1280 + i];
        g_s[i] = t;
    }
}

__global__ void squash_v_kernel(float* out_opt) {
    int t = threadIdx.x;
    if (t < 80) {
        int base = t * 16;
        float sv[16];
        float sq = 0.f;
#pragma unroll
        for (int jj = 0; jj < 16; jj++) { sv[jj] = g_s[base + jj]; sq += sv[jj] * sv[jj]; }
        float f = sq / (sqrtf(sq) * (1.f + sq));
#pragma unroll
        for (int jj = 0; jj < 16; jj++) {
            float vv = f * sv[jj];
            g_v[base + jj] = vv;
            if (out_opt) out_opt[base + jj] = vv;
        }
    }
}

// ---------------- decoder ----------------
__global__ void fc1_kernel(const float* __restrict__ target,
                           const float* __restrict__ w,
                           const float* __restrict__ bias) {
    int b = blockIdx.x;
    __shared__ float vm[16];
    if (threadIdx.x < 16) {
        float a = 0.f;
        for (int k = 0; k < 10; k++) a += target[b * 10 + k] * g_v[(b * 10 + k) * 16 + threadIdx.x];
        vm[threadIdx.x] = a;
    }
    __syncthreads();
    int o = threadIdx.x;
    float acc = bias[o];
#pragma unroll
    for (int i = 0; i < 16; i++) acc += vm[i] * w[o * 16 + i];
    g_h1[b * 512 + o] = fmaxf(acc, 0.f);
}

__global__ void fc2_kernel(const float* __restrict__ w, const float* __restrict__ bias) {
    int b = blockIdx.x;
    __shared__ float h1[512];
    if (threadIdx.x < 512) h1[threadIdx.x] = g_h1[b * 512 + threadIdx.x];
    __syncthreads();
    int o = threadIdx.x;
    float acc = bias[o];
    for (int i = 0; i < 512; i++) acc += h1[i] * w[o * 512 + i];
    g_h2[b * 1024 + o] = fmaxf(acc, 0.f);
}

__global__ void fc3_kernel(const float* __restrict__ w, const float* __restrict__ bias) {
    int b = blockIdx.y;
    int o = blockIdx.x * 256 + threadIdx.x;
    __shared__ float h2[1024];
    for (int i = threadIdx.x; i < 1024; i += 256) h2[i] = g_h2[b * 1024 + i];
    __syncthreads();
    if (o < 1296) {
        float acc = bias[o];
        for (int i = 0; i < 1024; i++) acc += h2[i] * w[o * 1024 + i];
        g_rec[b * 1296 + o] = 1.f / (1.f + expf(-acc));
    }
}

__global__ void upsample_kernel(float* __restrict__ out) {
    int idx = blockIdx.x * 256 + threadIdx.x;
    if (idx >= 8 * 5184) return;
    int b = idx / 5184;
    int r = idx - b * 5184;
    int oy = r / 72, ox = r - oy * 72;
    float sy = (float)(oy * 35) / 71.0f;
    float sx = (float)(ox * 35) / 71.0f;
    int y0 = (int)sy, x0 = (int)sx;
    int y1 = min(y0 + 1, 35), x1 = min(x0 + 1, 35);
    float wy = sy - (float)y0, wx = sx - (float)x0;
    const float* rb = g_rec + b * 1296;
    float a00 = rb[y0 * 36 + x0], a01 = rb[y0 * 36 + x1];
    float a10 = rb[y1 * 36 + x0], a11 = rb[y1 * 36 + x1];
    float v = (1.f - wy) * ((1.f - wx) * a00 + wx * a01) +
              wy * ((1.f - wx) * a10 + wx * a11);
    out[1280 + b * 5184 + r] = v;
}

// ---------------- launch ----------------
extern "C" void kernel_launch(void* const* d_in, const int* in_sizes, int n_in,
                              void* d_out, int out_size) {
    const float* x       = (const float*)d_in[0];
    const float* target  = (const float*)d_in[1];
    const float* conv1_w = (const float*)d_in[2];
    const float* conv1_b = (const float*)d_in[3];
    const float* pc1_w   = (const float*)d_in[4];
    const float* pc1_b   = (const float*)d_in[5];
    const float* pc2_w   = (const float*)d_in[6];
    const float* pc2_b   = (const float*)d_in[7];
    const float* pc3_w   = (const float*)d_in[8];
    const float* pc3_b   = (const float*)d_in[9];
    const float* W_digit = (const float*)d_in[10];
    const float* fc1_w   = (const float*)d_in[11];
    const float* fc1_b   = (const float*)d_in[12];
    const float* fc2_w   = (const float*)d_in[13];
    const float* fc2_b   = (const float*)d_in[14];
    const float* fc3_w   = (const float*)d_in[15];
    const float* fc3_b   = (const float*)d_in[16];
    float* out = (float*)d_out;

    float *conv1p, *pc1p, *pc2p, *pc3p, *up;
    __half* wpp;
    cudaGetSymbolAddress((void**)&conv1p, g_conv1);
    cudaGetSymbolAddress((void**)&wpp, g_wpadh);
    cudaGetSymbolAddress((void**)&pc1p, g_pc1);
    cudaGetSymbolAddress((void**)&pc2p, g_pc2);
    cudaGetSymbolAddress((void**)&pc3p, g_pc3);
    cudaGetSymbolAddress((void**)&up, g_u);

    conv1_kernel<<<dim3(256, 8), 256>>>(x, conv1_w, conv1_b, conv1p);
    wpad_kernel<<<16384, 256>>>(pc1_w, wpp);
    pc1_mma_kernel<<<dim3(8, 4, 8), 256>>>(conv1p, (const uint2*)wpp, pc1_b, pc1p);
    pc2_kernel<<<dim3(32, 8, 2), 256>>>(pc1p, pc2_w, pc2_b, pc2p);
    pc3_kernel<<<dim3(32, 8, 2), 256>>>(pc2p, pc3_w, pc3_b, pc3p);
    u_build_kernel<<<dim3(49, 8), 256>>>(pc3p, up);

    // routing iteration 1 (uniform c)
    routing_kernel<<<392, 256>>>(W_digit, 0);
    reduce_s_kernel<<<5, 256>>>();
    squash_v_kernel<<<1, 96>>>(nullptr);
    // routing iteration 2
    routing_kernel<<<392, 256>>>(W_digit, 1);
    reduce_s_kernel<<<5, 256>>>();
    squash_v_kernel<<<1, 96>>>(nullptr);
    // routing iteration 3 (final v -> d_out[0:1280])
    routing_kernel<<<392, 256>>>(W_digit, 2);
    reduce_s_kernel<<<5, 256>>>();
    squash_v_kernel<<<1, 96>>>(out);

    // decoder
    fc1_kernel<<<8, 512>>>(target, fc1_w, fc1_b);
    fc2_kernel<<<8, 1024>>>(fc2_w, fc2_b);
    fc3_kernel<<<dim3(6, 8), 256>>>(fc3_w, fc3_b);
    upsample_kernel<<<162, 256>>>(out);
}

// round 7
// speedup vs baseline: 2.5198x; 1.0060x over previous
#include <cuda_runtime.h>
#include <cuda_fp16.h>
#include <math.h>
#include <stdint.h>

// ---------------- scratch (static __device__, no allocations) ----------------
__device__ __half g_conv1h[8 * 256 * 64 * 64]; // [b][oc][64*64] fp16
__device__ __half g_wpadh[512 * 8192];         // pc1 weights fp16, K padded 25->32
__device__ float g_pc1[8 * 512 * 900];         // [b][oc][30*30]
__device__ float g_pc2[8 * 256 * 900];
__device__ float g_pc3[8 * 256 * 784];         // [b][oc][28*28]
__device__ float g_u[8 * 25088 * 8];           // squashed primary caps
__device__ float g_blog[8 * 25088 * 10];       // routing logits
__device__ float g_spart[392 * 1280];          // per-block partial s
__device__ float g_s[1280];
__device__ float g_v[1280];
__device__ float g_h1[8 * 512];
__device__ float g_h2[8 * 1024];
__device__ float g_rec[8 * 1296];

__device__ __forceinline__ void mma_fp16_16x8x16(float* d, const uint32_t* a,
                                                 uint32_t b0, uint32_t b1) {
    asm volatile(
        "mma.sync.aligned.m16n8k16.row.col.f32.f16.f16.f32 "
        "{%0,%1,%2,%3}, {%4,%5,%6,%7}, {%8,%9}, {%0,%1,%2,%3};"
        : "+f"(d[0]), "+f"(d[1]), "+f"(d[2]), "+f"(d[3])
        : "r"(a[0]), "r"(a[1]), "r"(a[2]), "r"(a[3]), "r"(b0), "r"(b1));
}

// ---------------- conv1: 1->256ch, 9x9, relu, fp16 out ----------------
__global__ void conv1_kernel(const float* __restrict__ x,
                             const float* __restrict__ w,
                             const float* __restrict__ bias,
                             __half* __restrict__ out) {
    int oc = blockIdx.x, b = blockIdx.y;
    __shared__ float xs[72 * 72];
    __shared__ float wsh[81];
    for (int i = threadIdx.x; i < 5184; i += 256) xs[i] = x[b * 5184 + i];
    if (threadIdx.x < 81) wsh[threadIdx.x] = w[oc * 81 + threadIdx.x];
    __syncthreads();
    float bv = bias[oc];
    for (int i = threadIdx.x; i < 4096; i += 256) {
        int oh = i >> 6, ow = i & 63;
        float acc = bv;
#pragma unroll
        for (int kh = 0; kh < 9; kh++)
#pragma unroll
            for (int kw = 0; kw < 9; kw++)
                acc += xs[(oh + kh) * 72 + ow + kw] * wsh[kh * 9 + kw];
        out[(b * 256 + oc) * 4096 + i] = __float2half(fmaxf(acc, 0.f));
    }
}

// ---------------- pc1 weight prep: pad 25->32, cvt fp16 (natural k order) ----------------
__global__ void wpad_kernel(const float* __restrict__ w, __half* __restrict__ wp) {
    int idx = blockIdx.x * 256 + threadIdx.x;
    if (idx >= 512 * 8192) return;
    int oc = idx >> 13, r = idx & 8191, ic = r >> 5, k = r & 31;
    float v = (k < 25) ? w[oc * 6400 + ic * 25 + k] : 0.f;
    wp[idx] = __float2half(v);
}

// ---------------- pc1 via mma.sync fp16 m16n8k16, double-buffered + prefetch ----------------
// block 256 thr = 8 warps; tile 128oc x 128sp; warp = 32oc x 64sp; K-chunk 32 (1 ic)
#define ASTR 40  // halves per row (80B) -> conflict-free fragment reads
__global__ void __launch_bounds__(256, 2)
pc1_mma_kernel(const __half* __restrict__ inh0, const uint2* __restrict__ wph2,
               const float* __restrict__ bias, float* __restrict__ out) {
    __shared__ __half As[2][128 * ASTR];
    __shared__ __half Bs[2][128 * ASTR];
    const int tid = threadIdx.x;
    const int lane = tid & 31, wid = tid >> 5;
    const int spt = blockIdx.x, oct = blockIdx.y, b = blockIdx.z;
    const int oc_base = oct * 128, sp_base = spt * 128;
    const int wm = wid & 3, wn = wid >> 2;

    // producer geometry: thread (rr 0..31, grp 0..7) covers rows 32q+rr, k = grp*4..grp*4+3
    const int rr = tid >> 3, grp = tid & 7;
    int eoff[4], eok[4];
#pragma unroll
    for (int t = 0; t < 4; t++) {
        int e = grp * 4 + t;
        eok[t] = (e < 25);
        int eh = e / 5, ew = e - eh * 5;
        eoff[t] = eh * 64 + ew;
    }
    int p0[4], bval[4];
#pragma unroll
    for (int q = 0; q < 4; q++) {
        int sp = sp_base + 32 * q + rr;
        bval[q] = (sp < 900);
        int oh = bval[q] ? sp / 30 : 0;
        int ow = bval[q] ? sp - oh * 30 : 0;
        p0[q] = oh * 128 + ow * 2;
    }
    const __half* inh = inh0 + (size_t)b * 256 * 4096;
    const uint2* wbase = wph2 + (size_t)oc_base * 2048;

    float acc[2][8][4];
#pragma unroll
    for (int mt = 0; mt < 2; mt++)
#pragma unroll
        for (int nt = 0; nt < 8; nt++)
#pragma unroll
            for (int i = 0; i < 4; i++) acc[mt][nt][i] = 0.f;

    const int gr = lane >> 2;        // fragment row/col group 0..7
    const int c2 = (lane & 3) * 2;   // k pair offset

    uint2 aR[4];
    __half bR[4][4];

    // preload chunk 0
#pragma unroll
    for (int q = 0; q < 4; q++)
        aR[q] = wbase[(size_t)(32 * q + rr) * 2048 + grp];
#pragma unroll
    for (int q = 0; q < 4; q++) {
        const __half* ip = inh + p0[q];
#pragma unroll
        for (int t = 0; t < 4; t++)
            bR[q][t] = (bval[q] && eok[t]) ? ip[eoff[t]] : __half(0.f);
    }

    for (int ic = 0; ic < 256; ic++) {
        const int bi = ic & 1;
        // store prefetched regs into buffer bi
#pragma unroll
        for (int q = 0; q < 4; q++)
            *(uint2*)&As[bi][(32 * q + rr) * ASTR + grp * 4] = aR[q];
#pragma unroll
        for (int q = 0; q < 4; q++) {
            __half2 h01 = __halves2half2(bR[q][0], bR[q][1]);
            __half2 h23 = __halves2half2(bR[q][2], bR[q][3]);
            uint2 bv;
            bv.x = *(uint32_t*)&h01;
            bv.y = *(uint32_t*)&h23;
            *(uint2*)&Bs[bi][(32 * q + rr) * ASTR + grp * 4] = bv;
        }
        // prefetch chunk ic+1 (overlaps with compute below)
        if (ic + 1 < 256) {
#pragma unroll
            for (int q = 0; q < 4; q++)
                aR[q] = wbase[(size_t)(32 * q + rr) * 2048 + (ic + 1) * 8 + grp];
            const __half* inc = inh + (ic + 1) * 4096;
#pragma unroll
            for (int q = 0; q < 4; q++) {
                const __half* ip = inc + p0[q];
#pragma unroll
                for (int t = 0; t < 4; t++)
                    bR[q][t] = (bval[q] && eok[t]) ? ip[eoff[t]] : __half(0.f);
            }
        }
        __syncthreads();
        // compute chunk ic from buffer bi (next store targets buffer bi^1 -> no WAR)
#pragma unroll
        for (int k16 = 0; k16 < 2; k16++) {
            int kb = k16 * 16 + c2;
            uint32_t afr[2][4];
#pragma unroll
            for (int mt = 0; mt < 2; mt++) {
                int r0 = (wm * 2 + mt) * 16 + gr;
                afr[mt][0] = *(const uint32_t*)&As[bi][r0 * ASTR + kb];
                afr[mt][1] = *(const uint32_t*)&As[bi][(r0 + 8) * ASTR + kb];
                afr[mt][2] = *(const uint32_t*)&As[bi][r0 * ASTR + kb + 8];
                afr[mt][3] = *(const uint32_t*)&As[bi][(r0 + 8) * ASTR + kb + 8];
            }
#pragma unroll
            for (int nt = 0; nt < 8; nt++) {
                int n = (wn * 8 + nt) * 8 + gr;
                uint32_t b0 = *(const uint32_t*)&Bs[bi][n * ASTR + kb];
                uint32_t b1 = *(const uint32_t*)&Bs[bi][n * ASTR + kb + 8];
                mma_fp16_16x8x16(acc[0][nt], afr[0], b0, b1);
                mma_fp16_16x8x16(acc[1][nt], afr[1], b0, b1);
            }
        }
    }
    // epilogue
#pragma unroll
    for (int mt = 0; mt < 2; mt++) {
        int oc0 = oc_base + (wm * 2 + mt) * 16 + gr;
        float b0 = bias[oc0], b1 = bias[oc0 + 8];
        float* op0 = out + ((size_t)b * 512 + oc0) * 900;
        float* op1 = out + ((size_t)b * 512 + oc0 + 8) * 900;
#pragma unroll
        for (int nt = 0; nt < 8; nt++) {
            int sp = sp_base + (wn * 8 + nt) * 8 + c2;
            if (sp < 900) {
                *(float2*)&op0[sp] = make_float2(acc[mt][nt][0] + b0, acc[mt][nt][1] + b0);
                *(float2*)&op1[sp] = make_float2(acc[mt][nt][2] + b1, acc[mt][nt][3] + b1);
            }
        }
    }
}

// ---------------- pc2: grouped 32g, 16->8, 3x3, pad 1 (3 row slices) ----------------
__global__ void pc2_kernel(const float* __restrict__ in,
                           const float* __restrict__ w,
                           const float* __restrict__ bias,
                           float* __restrict__ out) {
    int g = blockIdx.x, b = blockIdx.y, sl = blockIdx.z;
    int oh0 = sl * 10;
    __shared__ float wsh[1152];
    __shared__ float xin[16 * 12 * 30];
    for (int idx = threadIdx.x; idx < 1152; idx += 256) wsh[idx] = w[g * 1152 + idx];
    const float* inb = in + ((size_t)b * 512 + g * 16) * 900;
    for (int idx = threadIdx.x; idx < 5760; idx += 256) {
        int iw = idx % 30;
        int r2 = idx / 30;
        int ihl = r2 % 12, i = r2 / 12;
        int ih = oh0 - 1 + ihl;
        xin[idx] = (ih >= 0 && ih < 30) ? inb[i * 900 + ih * 30 + iw] : 0.f;
    }
    __syncthreads();
    for (int spl = threadIdx.x; spl < 300; spl += 256) {
        int ohl = spl / 30, ow = spl - ohl * 30;
        int oh = oh0 + ohl;
        float acc[8];
#pragma unroll
        for (int o = 0; o < 8; o++) acc[o] = bias[g * 8 + o];
        for (int i = 0; i < 16; i++) {
            const float* ip = xin + i * 360;
#pragma unroll
            for (int kh = 0; kh < 3; kh++) {
#pragma unroll
                for (int kw = 0; kw < 3; kw++) {
                    int iw = ow - 1 + kw;
                    if (iw < 0 || iw >= 30) continue;
                    float v = ip[(ohl + kh) * 30 + iw];
                    int e = kh * 3 + kw;
#pragma unroll
                    for (int o = 0; o < 8; o++) acc[o] += v * wsh[(o * 16 + i) * 9 + e];
                }
            }
        }
#pragma unroll
        for (int o = 0; o < 8; o++)
            out[((size_t)b * 256 + g * 8 + o) * 900 + oh * 30 + ow] = acc[o];
    }
}

// ---------------- pc3: grouped 32g, 8->8, 3x3, pad 0 (30->28), 4 row slices ----------------
__global__ void pc3_kernel(const float* __restrict__ in,
                           const float* __restrict__ w,
                           const float* __restrict__ bias,
                           float* __restrict__ out) {
    int g = blockIdx.x, b = blockIdx.y, sl = blockIdx.z;
    int oh0 = sl * 7;
    __shared__ float wsh[576];
    __shared__ float xin[8 * 9 * 30];
    for (int idx = threadIdx.x; idx < 576; idx += 256) wsh[idx] = w[g * 576 + idx];
    const float* inb = in + ((size_t)b * 256 + g * 8) * 900;
    for (int idx = threadIdx.x; idx < 2160; idx += 256) {
        int iw = idx % 30;
        int r2 = idx / 30;
        int ihl = r2 % 9, i = r2 / 9;
        xin[idx] = inb[i * 900 + (oh0 + ihl) * 30 + iw];
    }
    __syncthreads();
    for (int spl = threadIdx.x; spl < 196; spl += 256) {
        int ohl = spl / 28, ow = spl - ohl * 28;
        int oh = oh0 + ohl;
        float acc[8];
#pragma unroll
        for (int o = 0; o < 8; o++) acc[o] = bias[g * 8 + o];
        for (int i = 0; i < 8; i++) {
            const float* ip = xin + i * 270;
#pragma unroll
            for (int kh = 0; kh < 3; kh++) {
#pragma unroll
                for (int kw = 0; kw < 3; kw++) {
                    float v = ip[(ohl + kh) * 30 + ow + kw];
                    int e = kh * 3 + kw;
#pragma unroll
                    for (int o = 0; o < 8; o++) acc[o] += v * wsh[(o * 8 + i) * 9 + e];
                }
            }
        }
#pragma unroll
        for (int o = 0; o < 8; o++)
            out[((size_t)b * 256 + g * 8 + o) * 784 + oh * 28 + ow] = acc[o];
    }
}

// ---------------- build u (capsule transpose) + squash over dim 8 ----------------
__global__ void u_build_kernel(const float* __restrict__ y, float* __restrict__ u) {
    int b = blockIdx.y;
    int s0 = blockIdx.x * 16;
    __shared__ float ys[256 * 16];
    for (int i = threadIdx.x; i < 4096; i += 256) {
        int ch = i >> 4, si = i & 15;
        ys[i] = y[(b * 256 + ch) * 784 + s0 + si];
    }
    __syncthreads();
    for (int p = threadIdx.x; p < 512; p += 256) {
        int si = p >> 5, cap = p & 31;
        float d[8];
        float sq = 0.f;
#pragma unroll
        for (int i = 0; i < 8; i++) {
            d[i] = ys[(cap * 8 + i) * 16 + si];
            sq += d[i] * d[i];
        }
        float f = sq / (sqrtf(sq) * (1.f + sq));
        int n = (s0 + si) * 32 + cap;
        float* up = u + ((size_t)b * 25088 + n) * 8;
#pragma unroll
        for (int i = 0; i < 8; i++) up[i] = f * d[i];
    }
}

// ---------------- fused routing pass ----------------
__global__ void routing_kernel(const float* __restrict__ W, int mode) {
    int warp = (blockIdx.x * 256 + threadIdx.x) >> 5;
    int lane = threadIdx.x & 31;
    int bhalf = lane >> 4;
    int j = lane & 15;
    float s_acc[4][10];
#pragma unroll
    for (int bp = 0; bp < 4; bp++)
#pragma unroll
        for (int k = 0; k < 10; k++) s_acc[bp][k] = 0.f;

    int n0 = warp * 8;
    for (int nn = 0; nn < 8; nn++) {
        int n = n0 + nn;
        const float* Wn = W + (size_t)n * 1280;
#pragma unroll
        for (int bp = 0; bp < 4; bp++) {
            int b = bp * 2 + bhalf;
            const float* up = g_u + ((size_t)b * 25088 + n) * 8;
            float uu[8];
#pragma unroll
            for (int i = 0; i < 8; i++) uu[i] = up[i];
            float uh[10];
#pragma unroll
            for (int k = 0; k < 10; k++) {
                float a = 0.f;
#pragma unroll
                for (int i = 0; i < 8; i++) a += uu[i] * Wn[k * 128 + i * 16 + j];
                uh[k] = a;
            }
            float c[10];
            if (mode == 0) {
#pragma unroll
                for (int k = 0; k < 10; k++) c[k] = 0.1f;
            } else {
                float bl[10];
#pragma unroll
                for (int k = 0; k < 10; k++) {
                    float d = uh[k] * g_v[(b * 10 + k) * 16 + j];
                    d += __shfl_xor_sync(0xffffffffu, d, 1);
                    d += __shfl_xor_sync(0xffffffffu, d, 2);
                    d += __shfl_xor_sync(0xffffffffu, d, 4);
                    d += __shfl_xor_sync(0xffffffffu, d, 8);
                    bl[k] = d;
                }
                if (mode == 2) {
#pragma unroll
                    for (int k = 0; k < 10; k++)
                        bl[k] += g_blog[((size_t)b * 25088 + n) * 10 + k];
                } else if (j == 0) {
#pragma unroll
                    for (int k = 0; k < 10; k++)
                        g_blog[((size_t)b * 25088 + n) * 10 + k] = bl[k];
                }
                float m = bl[0];
#pragma unroll
                for (int k = 1; k < 10; k++) m = fmaxf(m, bl[k]);
                float sum = 0.f;
#pragma unroll
                for (int k = 0; k < 10; k++) { c[k] = expf(bl[k] - m); sum += c[k]; }
                float inv = 1.f / sum;
#pragma unroll
                for (int k = 0; k < 10; k++) c[k] *= inv;
            }
#pragma unroll
            for (int k = 0; k < 10; k++) s_acc[bp][k] += c[k] * uh[k];
        }
    }
    __shared__ float ssm[8][1280];
    int wl = (threadIdx.x >> 5);
#pragma unroll
    for (int bp = 0; bp < 4; bp++) {
        int b = bp * 2 + bhalf;
#pragma unroll
        for (int k = 0; k < 10; k++)
            ssm[wl][(b * 10 + k) * 16 + j] = s_acc[bp][k];
    }
    __syncthreads();
    for (int i = threadIdx.x; i < 1280; i += 256) {
        float t = 0.f;
#pragma unroll
        for (int w = 0; w < 8; w++) t += ssm[w][i];
        g_spart[blockIdx.x * 1280 + i] = t;
    }
}

__global__ void reduce_s_kernel() {
    int i = blockIdx.x * 256 + threadIdx.x;
    if (i < 1280) {
        float t = 0.f;
        for (int p = 0; p < 392; p++) t += g_spart[p * 1280 + i];
        g_s[i] = t;
    }
}

__global__ void squash_v_kernel(float* out_opt) {
    int t = threadIdx.x;
    if (t < 80) {
        int base = t * 16;
        float sv[16];
        float sq = 0.f;
#pragma unroll
        for (int jj = 0; jj < 16; jj++) { sv[jj] = g_s[base + jj]; sq += sv[jj] * sv[jj]; }
        float f = sq / (sqrtf(sq) * (1.f + sq));
#pragma unroll
        for (int jj = 0; jj < 16; jj++) {
            float vv = f * sv[jj];
            g_v[base + jj] = vv;
            if (out_opt) out_opt[base + jj] = vv;
        }
    }
}

// ---------------- decoder ----------------
__global__ void fc1_kernel(const float* __restrict__ target,
                           const float* __restrict__ w,
                           const float* __restrict__ bias) {
    int b = blockIdx.x;
    __shared__ float vm[16];
    if (threadIdx.x < 16) {
        float a = 0.f;
        for (int k = 0; k < 10; k++) a += target[b * 10 + k] * g_v[(b * 10 + k) * 16 + threadIdx.x];
        vm[threadIdx.x] = a;
    }
    __syncthreads();
    int o = threadIdx.x;
    float acc = bias[o];
#pragma unroll
    for (int i = 0; i < 16; i++) acc += vm[i] * w[o * 16 + i];
    g_h1[b * 512 + o] = fmaxf(acc, 0.f);
}

__global__ void fc2_kernel(const float* __restrict__ w, const float* __restrict__ bias) {
    int b = blockIdx.x;
    __shared__ float h1[512];
    if (threadIdx.x < 512) h1[threadIdx.x] = g_h1[b * 512 + threadIdx.x];
    __syncthreads();
    int o = threadIdx.x;
    float acc = bias[o];
    for (int i = 0; i < 512; i++) acc += h1[i] * w[o * 512 + i];
    g_h2[b * 1024 + o] = fmaxf(acc, 0.f);
}

__global__ void fc3_kernel(const float* __restrict__ w, const float* __restrict__ bias) {
    int b = blockIdx.y;
    int o = blockIdx.x * 256 + threadIdx.x;
    __shared__ float h2[1024];
    for (int i = threadIdx.x; i < 1024; i += 256) h2[i] = g_h2[b * 1024 + i];
    __syncthreads();
    if (o < 1296) {
        float acc = bias[o];
        for (int i = 0; i < 1024; i++) acc += h2[i] * w[o * 1024 + i];
        g_rec[b * 1296 + o] = 1.f / (1.f + expf(-acc));
    }
}

__global__ void upsample_kernel(float* __restrict__ out) {
    int idx = blockIdx.x * 256 + threadIdx.x;
    if (idx >= 8 * 5184) return;
    int b = idx / 5184;
    int r = idx - b * 5184;
    int oy = r / 72, ox = r - oy * 72;
    float sy = (float)(oy * 35) / 71.0f;
    float sx = (float)(ox * 35) / 71.0f;
    int y0 = (int)sy, x0 = (int)sx;
    int y1 = min(y0 + 1, 35), x1 = min(x0 + 1, 35);
    float wy = sy - (float)y0, wx = sx - (float)x0;
    const float* rb = g_rec + b * 1296;
    float a00 = rb[y0 * 36 + x0], a01 = rb[y0 * 36 + x1];
    float a10 = rb[y1 * 36 + x0], a11 = rb[y1 * 36 + x1];
    float v = (1.f - wy) * ((1.f - wx) * a00 + wx * a01) +
              wy * ((1.f - wx) * a10 + wx * a11);
    out[1280 + b * 5184 + r] = v;
}

// ---------------- launch ----------------
extern "C" void kernel_launch(void* const* d_in, const int* in_sizes, int n_in,
                              void* d_out, int out_size) {
    const float* x       = (const float*)d_in[0];
    const float* target  = (const float*)d_in[1];
    const float* conv1_w = (const float*)d_in[2];
    const float* conv1_b = (const float*)d_in[3];
    const float* pc1_w   = (const float*)d_in[4];
    const float* pc1_b   = (const float*)d_in[5];
    const float* pc2_w   = (const float*)d_in[6];
    const float* pc2_b   = (const float*)d_in[7];
    const float* pc3_w   = (const float*)d_in[8];
    const float* pc3_b   = (const float*)d_in[9];
    const float* W_digit = (const float*)d_in[10];
    const float* fc1_w   = (const float*)d_in[11];
    const float* fc1_b   = (const float*)d_in[12];
    const float* fc2_w   = (const float*)d_in[13];
    const float* fc2_b   = (const float*)d_in[14];
    const float* fc3_w   = (const float*)d_in[15];
    const float* fc3_b   = (const float*)d_in[16];
    float* out = (float*)d_out;

    float *pc1p, *pc2p, *pc3p, *up;
    __half *conv1p, *wpp;
    cudaGetSymbolAddress((void**)&conv1p, g_conv1h);
    cudaGetSymbolAddress((void**)&wpp, g_wpadh);
    cudaGetSymbolAddress((void**)&pc1p, g_pc1);
    cudaGetSymbolAddress((void**)&pc2p, g_pc2);
    cudaGetSymbolAddress((void**)&pc3p, g_pc3);
    cudaGetSymbolAddress((void**)&up, g_u);

    conv1_kernel<<<dim3(256, 8), 256>>>(x, conv1_w, conv1_b, conv1p);
    wpad_kernel<<<16384, 256>>>(pc1_w, wpp);
    pc1_mma_kernel<<<dim3(8, 4, 8), 256>>>(conv1p, (const uint2*)wpp, pc1_b, pc1p);
    pc2_kernel<<<dim3(32, 8, 3), 256>>>(pc1p, pc2_w, pc2_b, pc2p);
    pc3_kernel<<<dim3(32, 8, 4), 256>>>(pc2p, pc3_w, pc3_b, pc3p);
    u_build_kernel<<<dim3(49, 8), 256>>>(pc3p, up);

    // routing iteration 1 (uniform c)
    routing_kernel<<<392, 256>>>(W_digit, 0);
    reduce_s_kernel<<<5, 256>>>();
    squash_v_kernel<<<1, 96>>>(nullptr);
    // routing iteration 2
    routing_kernel<<<392, 256>>>(W_digit, 1);
    reduce_s_kernel<<<5, 256>>>();
    squash_v_kernel<<<1, 96>>>(nullptr);
    // routing iteration 3 (final v -> d_out[0:1280])
    routing_kernel<<<392, 256>>>(W_digit, 2);
    reduce_s_kernel<<<5, 256>>>();
    squash_v_kernel<<<1, 96>>>(out);

    // decoder
    fc1_kernel<<<8, 512>>>(target, fc1_w, fc1_b);
    fc2_kernel<<<8, 1024>>>(fc2_w, fc2_b);
    fc3_kernel<<<dim3(6, 8), 256>>>(fc3_w, fc3_b);
    upsample_kernel<<<162, 256>>>(out);
}

// round 8
// speedup vs baseline: 2.8622x; 1.1359x over previous
#include <cuda_runtime.h>
#include <cuda_fp16.h>
#include <math.h>
#include <stdint.h>

// ---------------- scratch (static __device__, no allocations) ----------------
__device__ __half g_conv1h[8 * 256 * 64 * 64]; // [b][oc][64*64] fp16
__device__ __half g_wpadh[512 * 8192];         // pc1 weights fp16, K padded 25->32
__device__ __half g_bmat[8 * 900 * 8192];      // im2col matrix [b][sp][k] fp16
__device__ float g_pc1[8 * 512 * 900];         // [b][oc][30*30]
__device__ float g_pc2[8 * 256 * 900];
__device__ float g_pc3[8 * 256 * 784];         // [b][oc][28*28]
__device__ float g_u[8 * 25088 * 8];           // squashed primary caps
__device__ float g_blog[8 * 25088 * 10];       // routing logits
__device__ float g_spart[392 * 1280];          // per-block partial s
__device__ float g_s[1280];
__device__ float g_v[1280];
__device__ float g_h1[8 * 512];
__device__ float g_h2[8 * 1024];
__device__ float g_rec[8 * 1296];

__device__ __forceinline__ void mma_fp16_16x8x16(float* d, const uint32_t* a,
                                                 uint32_t b0, uint32_t b1) {
    asm volatile(
        "mma.sync.aligned.m16n8k16.row.col.f32.f16.f16.f32 "
        "{%0,%1,%2,%3}, {%4,%5,%6,%7}, {%8,%9}, {%0,%1,%2,%3};"
        : "+f"(d[0]), "+f"(d[1]), "+f"(d[2]), "+f"(d[3])
        : "r"(a[0]), "r"(a[1]), "r"(a[2]), "r"(a[3]), "r"(b0), "r"(b1));
}

// ---------------- conv1: 1->256ch, 9x9, relu, fp16 out (register-tiled) ----------------
__global__ void conv1_kernel(const float* __restrict__ x,
                             const float* __restrict__ w,
                             const float* __restrict__ bias,
                             __half* __restrict__ out) {
    int oc = blockIdx.x, b = blockIdx.y;
    __shared__ float xs[72 * 72];
    __shared__ float wsh[81];
    for (int i = threadIdx.x; i < 5184; i += 256) xs[i] = x[b * 5184 + i];
    if (threadIdx.x < 81) wsh[threadIdx.x] = w[oc * 81 + threadIdx.x];
    __syncthreads();
    float bv = bias[oc];
    int og = threadIdx.x & 7;    // col group (8 x 8 cols)
    int r0 = threadIdx.x >> 3;   // row 0..31
    __half* ob = out + ((size_t)(b * 256 + oc)) * 4096;
    for (int hf = 0; hf < 2; hf++) {
        int oh = r0 + hf * 32;
        int ow0 = og * 8;
        float acc[8];
#pragma unroll
        for (int o = 0; o < 8; o++) acc[o] = bv;
#pragma unroll
        for (int kh = 0; kh < 9; kh++) {
            const float* row = &xs[(oh + kh) * 72 + ow0];
            float seg[16];
#pragma unroll
            for (int s = 0; s < 16; s += 4) {
                float4 v = *(const float4*)&row[s];
                seg[s] = v.x; seg[s + 1] = v.y; seg[s + 2] = v.z; seg[s + 3] = v.w;
            }
#pragma unroll
            for (int kw = 0; kw < 9; kw++) {
                float wv = wsh[kh * 9 + kw];
#pragma unroll
                for (int o = 0; o < 8; o++) acc[o] += seg[kw + o] * wv;
            }
        }
#pragma unroll
        for (int o = 0; o < 8; o++)
            ob[oh * 64 + ow0 + o] = __float2half(fmaxf(acc[o], 0.f));
    }
}

// ---------------- pc1 weight prep: pad 25->32, cvt fp16 (natural k order) ----------------
__global__ void wpad_kernel(const float* __restrict__ w, __half* __restrict__ wp) {
    int idx = blockIdx.x * 256 + threadIdx.x;
    if (idx >= 512 * 8192) return;
    int oc = idx >> 13, r = idx & 8191, ic = r >> 5, k = r & 31;
    float v = (k < 25) ? w[oc * 6400 + ic * 25 + k] : 0.f;
    wp[idx] = __float2half(v);
}

// ---------------- im2col: conv1h -> Bmat[b][sp][k], k padded 25->32 per ic ----------------
// block handles (oh, ic-chunk of 64, b); smem stages 64 ic x 5 rows x 64 cols
__global__ void im2col_kernel(const __half* __restrict__ ch, __half* __restrict__ bm) {
    int oh = blockIdx.x, icc = blockIdx.y, b = blockIdx.z;
    __shared__ __half sx[64 * 324];  // ic stride 324 halves (648B -> 2-way banks, 8B aligned)
    const __half* src = ch + ((size_t)(b * 256 + icc * 64)) * 4096 + (2 * oh) * 64;
    for (int idx = threadIdx.x; idx < 5120; idx += 256) {
        int c4 = idx & 15;
        int r = (idx >> 4) % 5;
        int ic = idx / 80;
        *(uint2*)&sx[ic * 324 + r * 64 + c4 * 4] =
            *(const uint2*)&src[(size_t)ic * 4096 + r * 64 + c4 * 4];
    }
    __syncthreads();
    __half* dstb = bm + ((size_t)b * 900 + oh * 30) * 8192 + icc * 64 * 32;
    for (int idx = threadIdx.x; idx < 1920; idx += 256) {
        int ic = idx & 63, ow = idx >> 6;
        __half hv[32];
#pragma unroll
        for (int e = 0; e < 25; e++)
            hv[e] = sx[ic * 324 + (e / 5) * 64 + 2 * ow + (e % 5)];
#pragma unroll
        for (int e = 25; e < 32; e++) hv[e] = __half(0.f);
        uint32_t pk[16];
#pragma unroll
        for (int t = 0; t < 16; t++) {
            __half2 p = __halves2half2(hv[2 * t], hv[2 * t + 1]);
            pk[t] = *(uint32_t*)&p;
        }
        uint4* dst = (uint4*)(dstb + (size_t)ow * 8192 + ic * 32);
        dst[0] = make_uint4(pk[0], pk[1], pk[2], pk[3]);
        dst[1] = make_uint4(pk[4], pk[5], pk[6], pk[7]);
        dst[2] = make_uint4(pk[8], pk[9], pk[10], pk[11]);
        dst[3] = make_uint4(pk[12], pk[13], pk[14], pk[15]);
    }
}

// ---------------- pc1 via mma.sync fp16 m16n8k16, double-buffered + prefetch ----------------
// block 256 thr = 8 warps; tile 128oc x 128sp; warp = 32oc x 64sp; K-chunk 32 (1 ic)
#define ASTR 40  // halves per row (80B) -> conflict-free fragment reads
__global__ void __launch_bounds__(256, 2)
pc1_mma_kernel(const __half* __restrict__ bmat, const uint2* __restrict__ wph2,
               const float* __restrict__ bias, float* __restrict__ out) {
    __shared__ __half As[2][128 * ASTR];
    __shared__ __half Bs[2][128 * ASTR];
    const int tid = threadIdx.x;
    const int lane = tid & 31, wid = tid >> 5;
    const int spt = blockIdx.x, oct = blockIdx.y, b = blockIdx.z;
    const int oc_base = oct * 128, sp_base = spt * 128;
    const int wm = wid & 3, wn = wid >> 2;

    // producer geometry: thread (rr 0..31, grp 0..7) covers rows 32q+rr, k = grp*4..grp*4+3
    const int rr = tid >> 3, grp = tid & 7;
    const uint2* bb[4];
    int bval[4];
#pragma unroll
    for (int q = 0; q < 4; q++) {
        int sp = sp_base + 32 * q + rr;
        bval[q] = (sp < 900);
        bb[q] = (const uint2*)(bmat + ((size_t)b * 900 + (bval[q] ? sp : 0)) * 8192) + grp;
    }
    const uint2* wbase = wph2 + (size_t)oc_base * 2048;

    float acc[2][8][4];
#pragma unroll
    for (int mt = 0; mt < 2; mt++)
#pragma unroll
        for (int nt = 0; nt < 8; nt++)
#pragma unroll
            for (int i = 0; i < 4; i++) acc[mt][nt][i] = 0.f;

    const int gr = lane >> 2;        // fragment row/col group 0..7
    const int c2 = (lane & 3) * 2;   // k pair offset

    uint2 aR[4], bR[4];
    const uint2 z2 = make_uint2(0u, 0u);

    // preload chunk 0
#pragma unroll
    for (int q = 0; q < 4; q++)
        aR[q] = wbase[(size_t)(32 * q + rr) * 2048 + grp];
#pragma unroll
    for (int q = 0; q < 4; q++)
        bR[q] = bval[q] ? bb[q][0] : z2;

    for (int ic = 0; ic < 256; ic++) {
        const int bi = ic & 1;
        // store prefetched regs into buffer bi
#pragma unroll
        for (int q = 0; q < 4; q++)
            *(uint2*)&As[bi][(32 * q + rr) * ASTR + grp * 4] = aR[q];
#pragma unroll
        for (int q = 0; q < 4; q++)
            *(uint2*)&Bs[bi][(32 * q + rr) * ASTR + grp * 4] = bR[q];
        // prefetch chunk ic+1 (overlaps with compute below)
        if (ic + 1 < 256) {
#pragma unroll
            for (int q = 0; q < 4; q++)
                aR[q] = wbase[(size_t)(32 * q + rr) * 2048 + (ic + 1) * 8 + grp];
#pragma unroll
            for (int q = 0; q < 4; q++)
                bR[q] = bval[q] ? bb[q][(ic + 1) * 8] : z2;
        }
        __syncthreads();
        // compute chunk ic from buffer bi (next store targets buffer bi^1 -> no WAR)
#pragma unroll
        for (int k16 = 0; k16 < 2; k16++) {
            int kb = k16 * 16 + c2;
            uint32_t afr[2][4];
#pragma unroll
            for (int mt = 0; mt < 2; mt++) {
                int r0 = (wm * 2 + mt) * 16 + gr;
                afr[mt][0] = *(const uint32_t*)&As[bi][r0 * ASTR + kb];
                afr[mt][1] = *(const uint32_t*)&As[bi][(r0 + 8) * ASTR + kb];
                afr[mt][2] = *(const uint32_t*)&As[bi][r0 * ASTR + kb + 8];
                afr[mt][3] = *(const uint32_t*)&As[bi][(r0 + 8) * ASTR + kb + 8];
            }
#pragma unroll
            for (int nt = 0; nt < 8; nt++) {
                int n = (wn * 8 + nt) * 8 + gr;
                uint32_t b0 = *(const uint32_t*)&Bs[bi][n * ASTR + kb];
                uint32_t b1 = *(const uint32_t*)&Bs[bi][n * ASTR + kb + 8];
                mma_fp16_16x8x16(acc[0][nt], afr[0], b0, b1);
                mma_fp16_16x8x16(acc[1][nt], afr[1], b0, b1);
            }
        }
    }
    // epilogue
#pragma unroll
    for (int mt = 0; mt < 2; mt++) {
        int oc0 = oc_base + (wm * 2 + mt) * 16 + gr;
        float b0 = bias[oc0], b1 = bias[oc0 + 8];
        float* op0 = out + ((size_t)b * 512 + oc0) * 900;
        float* op1 = out + ((size_t)b * 512 + oc0 + 8) * 900;
#pragma unroll
        for (int nt = 0; nt < 8; nt++) {
            int sp = sp_base + (wn * 8 + nt) * 8 + c2;
            if (sp < 900) {
                *(float2*)&op0[sp] = make_float2(acc[mt][nt][0] + b0, acc[mt][nt][1] + b0);
                *(float2*)&op1[sp] = make_float2(acc[mt][nt][2] + b1, acc[mt][nt][3] + b1);
            }
        }
    }
}

// ---------------- pc2: grouped 32g, 16->8, 3x3, pad 1 (3 row slices) ----------------
__global__ void pc2_kernel(const float* __restrict__ in,
                           const float* __restrict__ w,
                           const float* __restrict__ bias,
                           float* __restrict__ out) {
    int g = blockIdx.x, b = blockIdx.y, sl = blockIdx.z;
    int oh0 = sl * 10;
    __shared__ float wsh[1152];
    __shared__ float xin[16 * 12 * 30];
    for (int idx = threadIdx.x; idx < 1152; idx += 256) wsh[idx] = w[g * 1152 + idx];
    const float* inb = in + ((size_t)b * 512 + g * 16) * 900;
    for (int idx = threadIdx.x; idx < 5760; idx += 256) {
        int iw = idx % 30;
        int r2 = idx / 30;
        int ihl = r2 % 12, i = r2 / 12;
        int ih = oh0 - 1 + ihl;
        xin[idx] = (ih >= 0 && ih < 30) ? inb[i * 900 + ih * 30 + iw] : 0.f;
    }
    __syncthreads();
    for (int spl = threadIdx.x; spl < 300; spl += 256) {
        int ohl = spl / 30, ow = spl - ohl * 30;
        int oh = oh0 + ohl;
        float acc[8];
#pragma unroll
        for (int o = 0; o < 8; o++) acc[o] = bias[g * 8 + o];
        for (int i = 0; i < 16; i++) {
            const float* ip = xin + i * 360;
#pragma unroll
            for (int kh = 0; kh < 3; kh++) {
#pragma unroll
                for (int kw = 0; kw < 3; kw++) {
                    int iw = ow - 1 + kw;
                    if (iw < 0 || iw >= 30) continue;
                    float v = ip[(ohl + kh) * 30 + iw];
                    int e = kh * 3 + kw;
#pragma unroll
                    for (int o = 0; o < 8; o++) acc[o] += v * wsh[(o * 16 + i) * 9 + e];
                }
            }
        }
#pragma unroll
        for (int o = 0; o < 8; o++)
            out[((size_t)b * 256 + g * 8 + o) * 900 + oh * 30 + ow] = acc[o];
    }
}

// ---------------- pc3: grouped 32g, 8->8, 3x3, pad 0 (30->28), 4 row slices ----------------
__global__ void pc3_kernel(const float* __restrict__ in,
                           const float* __restrict__ w,
                           const float* __restrict__ bias,
                           float* __restrict__ out) {
    int g = blockIdx.x, b = blockIdx.y, sl = blockIdx.z;
    int oh0 = sl * 7;
    __shared__ float wsh[576];
    __shared__ float xin[8 * 9 * 30];
    for (int idx = threadIdx.x; idx < 576; idx += 256) wsh[idx] = w[g * 576 + idx];
    const float* inb = in + ((size_t)b * 256 + g * 8) * 900;
    for (int idx = threadIdx.x; idx < 2160; idx += 256) {
        int iw = idx % 30;
        int r2 = idx / 30;
        int ihl = r2 % 9, i = r2 / 9;
        xin[idx] = inb[i * 900 + (oh0 + ihl) * 30 + iw];
    }
    __syncthreads();
    for (int spl = threadIdx.x; spl < 196; spl += 256) {
        int ohl = spl / 28, ow = spl - ohl * 28;
        int oh = oh0 + ohl;
        float acc[8];
#pragma unroll
        for (int o = 0; o < 8; o++) acc[o] = bias[g * 8 + o];
        for (int i = 0; i < 8; i++) {
            const float* ip = xin + i * 270;
#pragma unroll
            for (int kh = 0; kh < 3; kh++) {
#pragma unroll
                for (int kw = 0; kw < 3; kw++) {
                    float v = ip[(ohl + kh) * 30 + ow + kw];
                    int e = kh * 3 + kw;
#pragma unroll
                    for (int o = 0; o < 8; o++) acc[o] += v * wsh[(o * 8 + i) * 9 + e];
                }
            }
        }
#pragma unroll
        for (int o = 0; o < 8; o++)
            out[((size_t)b * 256 + g * 8 + o) * 784 + oh * 28 + ow] = acc[o];
    }
}

// ---------------- build u (capsule transpose) + squash over dim 8 ----------------
__global__ void u_build_kernel(const float* __restrict__ y, float* __restrict__ u) {
    int b = blockIdx.y;
    int s0 = blockIdx.x * 16;
    __shared__ float ys[256 * 16];
    for (int i = threadIdx.x; i < 4096; i += 256) {
        int ch = i >> 4, si = i & 15;
        ys[i] = y[(b * 256 + ch) * 784 + s0 + si];
    }
    __syncthreads();
    for (int p = threadIdx.x; p < 512; p += 256) {
        int si = p >> 5, cap = p & 31;
        float d[8];
        float sq = 0.f;
#pragma unroll
        for (int i = 0; i < 8; i++) {
            d[i] = ys[(cap * 8 + i) * 16 + si];
            sq += d[i] * d[i];
        }
        float f = sq / (sqrtf(sq) * (1.f + sq));
        int n = (s0 + si) * 32 + cap;
        float* up = u + ((size_t)b * 25088 + n) * 8;
#pragma unroll
        for (int i = 0; i < 8; i++) up[i] = f * d[i];
    }
}

// ---------------- fused routing pass ----------------
__global__ void routing_kernel(const float* __restrict__ W, int mode) {
    int warp = (blockIdx.x * 256 + threadIdx.x) >> 5;
    int lane = threadIdx.x & 31;
    int bhalf = lane >> 4;
    int j = lane & 15;
    float s_acc[4][10];
#pragma unroll
    for (int bp = 0; bp < 4; bp++)
#pragma unroll
        for (int k = 0; k < 10; k++) s_acc[bp][k] = 0.f;

    int n0 = warp * 8;
    for (int nn = 0; nn < 8; nn++) {
        int n = n0 + nn;
        const float* Wn = W + (size_t)n * 1280;
#pragma unroll
        for (int bp = 0; bp < 4; bp++) {
            int b = bp * 2 + bhalf;
            const float* up = g_u + ((size_t)b * 25088 + n) * 8;
            float uu[8];
#pragma unroll
            for (int i = 0; i < 8; i++) uu[i] = up[i];
            float uh[10];
#pragma unroll
            for (int k = 0; k < 10; k++) {
                float a = 0.f;
#pragma unroll
                for (int i = 0; i < 8; i++) a += uu[i] * Wn[k * 128 + i * 16 + j];
                uh[k] = a;
            }
            float c[10];
            if (mode == 0) {
#pragma unroll
                for (int k = 0; k < 10; k++) c[k] = 0.1f;
            } else {
                float bl[10];
#pragma unroll
                for (int k = 0; k < 10; k++) {
                    float d = uh[k] * g_v[(b * 10 + k) * 16 + j];
                    d += __shfl_xor_sync(0xffffffffu, d, 1);
                    d += __shfl_xor_sync(0xffffffffu, d, 2);
                    d += __shfl_xor_sync(0xffffffffu, d, 4);
                    d += __shfl_xor_sync(0xffffffffu, d, 8);
                    bl[k] = d;
                }
                if (mode == 2) {
#pragma unroll
                    for (int k = 0; k < 10; k++)
                        bl[k] += g_blog[((size_t)b * 25088 + n) * 10 + k];
                } else if (j == 0) {
#pragma unroll
                    for (int k = 0; k < 10; k++)
                        g_blog[((size_t)b * 25088 + n) * 10 + k] = bl[k];
                }
                float m = bl[0];
#pragma unroll
                for (int k = 1; k < 10; k++) m = fmaxf(m, bl[k]);
                float sum = 0.f;
#pragma unroll
                for (int k = 0; k < 10; k++) { c[k] = expf(bl[k] - m); sum += c[k]; }
                float inv = 1.f / sum;
#pragma unroll
                for (int k = 0; k < 10; k++) c[k] *= inv;
            }
#pragma unroll
            for (int k = 0; k < 10; k++) s_acc[bp][k] += c[k] * uh[k];
        }
    }
    __shared__ float ssm[8][1280];
    int wl = (threadIdx.x >> 5);
#pragma unroll
    for (int bp = 0; bp < 4; bp++) {
        int b = bp * 2 + bhalf;
#pragma unroll
        for (int k = 0; k < 10; k++)
            ssm[wl][(b * 10 + k) * 16 + j] = s_acc[bp][k];
    }
    __syncthreads();
    for (int i = threadIdx.x; i < 1280; i += 256) {
        float t = 0.f;
#pragma unroll
        for (int w = 0; w < 8; w++) t += ssm[w][i];
        g_spart[blockIdx.x * 1280 + i] = t;
    }
}

__global__ void reduce_s_kernel() {
    int i = blockIdx.x * 256 + threadIdx.x;
    if (i < 1280) {
        float t = 0.f;
        for (int p = 0; p < 392; p++) t += g_spart[p * 1280 + i];
        g_s[i] = t;
    }
}

__global__ void squash_v_kernel(float* out_opt) {
    int t = threadIdx.x;
    if (t < 80) {
        int base = t * 16;
        float sv[16];
        float sq = 0.f;
#pragma unroll
        for (int jj = 0; jj < 16; jj++) { sv[jj] = g_s[base + jj]; sq += sv[jj] * sv[jj]; }
        float f = sq / (sqrtf(sq) * (1.f + sq));
#pragma unroll
        for (int jj = 0; jj < 16; jj++) {
            float vv = f * sv[jj];
            g_v[base + jj] = vv;
            if (out_opt) out_opt[base + jj] = vv;
        }
    }
}

// ---------------- decoder ----------------
__global__ void fc1_kernel(const float* __restrict__ target,
                           const float* __restrict__ w,
                           const float* __restrict__ bias) {
    int b = blockIdx.x;
    __shared__ float vm[16];
    if (threadIdx.x < 16) {
        float a = 0.f;
        for (int k = 0; k < 10; k++) a += target[b * 10 + k] * g_v[(b * 10 + k) * 16 + threadIdx.x];
        vm[threadIdx.x] = a;
    }
    __syncthreads();
    int o = threadIdx.x;
    float acc = bias[o];
#pragma unroll
    for (int i = 0; i < 16; i++) acc += vm[i] * w[o * 16 + i];
    g_h1[b * 512 + o] = fmaxf(acc, 0.f);
}

__global__ void fc2_kernel(const float* __restrict__ w, const float* __restrict__ bias) {
    int b = blockIdx.x;
    __shared__ float h1[512];
    if (threadIdx.x < 512) h1[threadIdx.x] = g_h1[b * 512 + threadIdx.x];
    __syncthreads();
    int o = threadIdx.x;
    float acc = bias[o];
    for (int i = 0; i < 512; i++) acc += h1[i] * w[o * 512 + i];
    g_h2[b * 1024 + o] = fmaxf(acc, 0.f);
}

__global__ void fc3_kernel(const float* __restrict__ w, const float* __restrict__ bias) {
    int b = blockIdx.y;
    int o = blockIdx.x * 256 + threadIdx.x;
    __shared__ float h2[1024];
    for (int i = threadIdx.x; i < 1024; i += 256) h2[i] = g_h2[b * 1024 + i];
    __syncthreads();
    if (o < 1296) {
        float acc = bias[o];
        for (int i = 0; i < 1024; i++) acc += h2[i] * w[o * 1024 + i];
        g_rec[b * 1296 + o] = 1.f / (1.f + expf(-acc));
    }
}

__global__ void upsample_kernel(float* __restrict__ out) {
    int idx = blockIdx.x * 256 + threadIdx.x;
    if (idx >= 8 * 5184) return;
    int b = idx / 5184;
    int r = idx - b * 5184;
    int oy = r / 72, ox = r - oy * 72;
    float sy = (float)(oy * 35) / 71.0f;
    float sx = (float)(ox * 35) / 71.0f;
    int y0 = (int)sy, x0 = (int)sx;
    int y1 = min(y0 + 1, 35), x1 = min(x0 + 1, 35);
    float wy = sy - (float)y0, wx = sx - (float)x0;
    const float* rb = g_rec + b * 1296;
    float a00 = rb[y0 * 36 + x0], a01 = rb[y0 * 36 + x1];
    float a10 = rb[y1 * 36 + x0], a11 = rb[y1 * 36 + x1];
    float v = (1.f - wy) * ((1.f - wx) * a00 + wx * a01) +
              wy * ((1.f - wx) * a10 + wx * a11);
    out[1280 + b * 5184 + r] = v;
}

// ---------------- launch ----------------
extern "C" void kernel_launch(void* const* d_in, const int* in_sizes, int n_in,
                              void* d_out, int out_size) {
    const float* x       = (const float*)d_in[0];
    const float* target  = (const float*)d_in[1];
    const float* conv1_w = (const float*)d_in[2];
    const float* conv1_b = (const float*)d_in[3];
    const float* pc1_w   = (const float*)d_in[4];
    const float* pc1_b   = (const float*)d_in[5];
    const float* pc2_w   = (const float*)d_in[6];
    const float* pc2_b   = (const float*)d_in[7];
    const float* pc3_w   = (const float*)d_in[8];
    const float* pc3_b   = (const float*)d_in[9];
    const float* W_digit = (const float*)d_in[10];
    const float* fc1_w   = (const float*)d_in[11];
    const float* fc1_b   = (const float*)d_in[12];
    const float* fc2_w   = (const float*)d_in[13];
    const float* fc2_b   = (const float*)d_in[14];
    const float* fc3_w   = (const float*)d_in[15];
    const float* fc3_b   = (const float*)d_in[16];
    float* out = (float*)d_out;

    float *pc1p, *pc2p, *pc3p, *up;
    __half *conv1p, *wpp, *bmp;
    cudaGetSymbolAddress((void**)&conv1p, g_conv1h);
    cudaGetSymbolAddress((void**)&wpp, g_wpadh);
    cudaGetSymbolAddress((void**)&bmp, g_bmat);
    cudaGetSymbolAddress((void**)&pc1p, g_pc1);
    cudaGetSymbolAddress((void**)&pc2p, g_pc2);
    cudaGetSymbolAddress((void**)&pc3p, g_pc3);
    cudaGetSymbolAddress((void**)&up, g_u);

    conv1_kernel<<<dim3(256, 8), 256>>>(x, conv1_w, conv1_b, conv1p);
    wpad_kernel<<<16384, 256>>>(pc1_w, wpp);
    im2col_kernel<<<dim3(30, 4, 8), 256>>>(conv1p, bmp);
    pc1_mma_kernel<<<dim3(8, 4, 8), 256>>>(bmp, (const uint2*)wpp, pc1_b, pc1p);
    pc2_kernel<<<dim3(32, 8, 3), 256>>>(pc1p, pc2_w, pc2_b, pc2p);
    pc3_kernel<<<dim3(32, 8, 4), 256>>>(pc2p, pc3_w, pc3_b, pc3p);
    u_build_kernel<<<dim3(49, 8), 256>>>(pc3p, up);

    // routing iteration 1 (uniform c)
    routing_kernel<<<392, 256>>>(W_digit, 0);
    reduce_s_kernel<<<5, 256>>>();
    squash_v_kernel<<<1, 96>>>(nullptr);
    // routing iteration 2
    routing_kernel<<<392, 256>>>(W_digit, 1);
    reduce_s_kernel<<<5, 256>>>();
    squash_v_kernel<<<1, 96>>>(nullptr);
    // routing iteration 3 (final v -> d_out[0:1280])
    routing_kernel<<<392, 256>>>(W_digit, 2);
    reduce_s_kernel<<<5, 256>>>();
    squash_v_kernel<<<1, 96>>>(out);

    // decoder
    fc1_kernel<<<8, 512>>>(target, fc1_w, fc1_b);
    fc2_kernel<<<8, 1024>>>(fc2_w, fc2_b);
    fc3_kernel<<<dim3(6, 8), 256>>>(fc3_w, fc3_b);
    upsample_kernel<<<162, 256>>>(out);
}